// round 1
// baseline (speedup 1.0000x reference)
#include <cuda_runtime.h>
#include <cuda_bf16.h>

// Problem constants (fixed by the reference)
#define BATCH   4
#define SEQ     4096
#define DMODEL  1024
#define DK      64
#define ROWS    (BATCH * SEQ)        // 16384
#define PITCH   65                   // smem pitch to dodge bank conflicts

// Scratch for projected q/k/v  (3 x 4 MB, static __device__ per allocation rules)
__device__ float g_qh[ROWS * DK];
__device__ float g_kh[ROWS * DK];
__device__ float g_vh[ROWS * DK];

// ---------------------------------------------------------------------------
// Projection: Y[row, 0:64] = (X[row, 0:1024] @ W[1024,64] + b)  (* m[row]/8 for q)
// Block: 256 threads, computes 64 rows x 64 cols. 4x4 register micro-tile.
// which: 0 -> g_qh (apply mask*0.125), 1 -> g_kh, 2 -> g_vh
// ---------------------------------------------------------------------------
__global__ __launch_bounds__(256) void proj_kernel(
    const float* __restrict__ X,
    const float* __restrict__ W,
    const float* __restrict__ bias,
    const float* __restrict__ mask,   // nullptr for k/v
    int which)
{
    __shared__ float Xs[64][PITCH];
    __shared__ float Ws[64][PITCH];

    float* Y = (which == 0) ? g_qh : (which == 1) ? g_kh : g_vh;

    const int tid  = threadIdx.x;
    const int row0 = blockIdx.x * 64;
    const int ty   = tid >> 4;      // 0..15
    const int tx   = tid & 15;      // 0..15

    float acc[4][4];
#pragma unroll
    for (int i = 0; i < 4; i++)
#pragma unroll
        for (int j = 0; j < 4; j++) acc[i][j] = 0.f;

    for (int k0 = 0; k0 < DMODEL; k0 += 64) {
        __syncthreads();
#pragma unroll
        for (int i = 0; i < 16; i++) {
            int idx = tid + i * 256;
            int r = idx >> 6, c = idx & 63;
            Xs[r][c] = X[(size_t)(row0 + r) * DMODEL + k0 + c];
            Ws[r][c] = W[(size_t)(k0 + r) * DK + c];
        }
        __syncthreads();
#pragma unroll 8
        for (int kk = 0; kk < 64; kk++) {
            float a[4], b[4];
#pragma unroll
            for (int i = 0; i < 4; i++) a[i] = Xs[ty * 4 + i][kk];
#pragma unroll
            for (int j = 0; j < 4; j++) b[j] = Ws[kk][tx * 4 + j];
#pragma unroll
            for (int i = 0; i < 4; i++)
#pragma unroll
                for (int j = 0; j < 4; j++) acc[i][j] += a[i] * b[j];
        }
    }

#pragma unroll
    for (int i = 0; i < 4; i++) {
        int r = row0 + ty * 4 + i;
        // fold mask and 1/sqrt(dk) into q-hat rows
        float sc = (mask != nullptr) ? (mask[r] * 0.125f) : 1.0f;
#pragma unroll
        for (int j = 0; j < 4; j++) {
            int c = tx * 4 + j;
            Y[(size_t)r * DK + c] = (acc[i][j] + bias[c]) * sc;
        }
    }
}

// ---------------------------------------------------------------------------
// Flash attention: block handles (batch b, 64-query tile). Online softmax.
// Logits already scaled (mask/sqrt(dk) folded into qh).
// ---------------------------------------------------------------------------
#define ATTN_SMEM_FLOATS (4 * 64 * PITCH + 3 * 64)
#define ATTN_SMEM_BYTES  (ATTN_SMEM_FLOATS * (int)sizeof(float))

__global__ __launch_bounds__(256) void attn_kernel(float* __restrict__ out)
{
    extern __shared__ float sm[];
    float* Qs   = sm;                    // [64][PITCH]
    float* Ks   = Qs + 64 * PITCH;       // [64][PITCH]
    float* Vs   = Ks + 64 * PITCH;       // [64][PITCH]
    float* Ps   = Vs + 64 * PITCH;       // [64][PITCH] scores -> probs
    float* rowM = Ps + 64 * PITCH;       // [64]
    float* rowL = rowM + 64;             // [64]
    float* rowC = rowL + 64;             // [64]

    const int tid = threadIdx.x;
    const int b   = blockIdx.y;
    const int q0  = blockIdx.x * 64;
    const int ty  = tid >> 4;
    const int tx  = tid & 15;

    const float* qb = g_qh + ((size_t)b * SEQ + q0) * DK;
    const float* kb = g_kh + (size_t)b * SEQ * DK;
    const float* vb = g_vh + (size_t)b * SEQ * DK;

    // load Q tile
#pragma unroll
    for (int i = 0; i < 16; i++) {
        int idx = tid + i * 256;
        int r = idx >> 6, c = idx & 63;
        Qs[r * PITCH + c] = qb[(size_t)r * DK + c];
    }
    if (tid < 64) { rowM[tid] = -1e30f; rowL[tid] = 0.f; }

    float acc[4][4];
#pragma unroll
    for (int i = 0; i < 4; i++)
#pragma unroll
        for (int j = 0; j < 4; j++) acc[i][j] = 0.f;

    for (int kt = 0; kt < SEQ / 64; kt++) {
        __syncthreads();   // prev PV done (reads Ps/Vs); also orders Q-load/init
        // load K and V tiles for this step
#pragma unroll
        for (int i = 0; i < 16; i++) {
            int idx = tid + i * 256;
            int r = idx >> 6, c = idx & 63;
            Ks[r * PITCH + c] = kb[(size_t)(kt * 64 + r) * DK + c];
            Vs[r * PITCH + c] = vb[(size_t)(kt * 64 + r) * DK + c];
        }
        __syncthreads();

        // scores S = Qs @ Ks^T   (logits already scaled)
        float s[4][4];
#pragma unroll
        for (int i = 0; i < 4; i++)
#pragma unroll
            for (int j = 0; j < 4; j++) s[i][j] = 0.f;
#pragma unroll 8
        for (int kk = 0; kk < 64; kk++) {
            float a[4], c[4];
#pragma unroll
            for (int i = 0; i < 4; i++) a[i] = Qs[(ty * 4 + i) * PITCH + kk];
#pragma unroll
            for (int j = 0; j < 4; j++) c[j] = Ks[(tx * 4 + j) * PITCH + kk];
#pragma unroll
            for (int i = 0; i < 4; i++)
#pragma unroll
                for (int j = 0; j < 4; j++) s[i][j] += a[i] * c[j];
        }
#pragma unroll
        for (int i = 0; i < 4; i++)
#pragma unroll
            for (int j = 0; j < 4; j++)
                Ps[(ty * 4 + i) * PITCH + tx * 4 + j] = s[i][j];
        __syncthreads();

        // online softmax: 4 threads per row
        {
            const int row = tid >> 2;
            const int sub = tid & 3;
            float* prow = Ps + row * PITCH + sub * 16;
            float mloc = -1e30f;
#pragma unroll
            for (int t = 0; t < 16; t++) mloc = fmaxf(mloc, prow[t]);
            mloc = fmaxf(mloc, __shfl_xor_sync(0xffffffffu, mloc, 1));
            mloc = fmaxf(mloc, __shfl_xor_sync(0xffffffffu, mloc, 2));
            float mprev = rowM[row];
            float mnew  = fmaxf(mprev, mloc);
            float corr  = __expf(mprev - mnew);
            float lsum  = 0.f;
#pragma unroll
            for (int t = 0; t < 16; t++) {
                float p = __expf(prow[t] - mnew);
                prow[t] = p;
                lsum += p;
            }
            lsum += __shfl_xor_sync(0xffffffffu, lsum, 1);
            lsum += __shfl_xor_sync(0xffffffffu, lsum, 2);
            if (sub == 0) {
                rowL[row] = rowL[row] * corr + lsum;
                rowM[row] = mnew;
                rowC[row] = corr;
            }
        }
        __syncthreads();

        // rescale accumulators and add P @ V
        float cr[4];
#pragma unroll
        for (int i = 0; i < 4; i++) cr[i] = rowC[ty * 4 + i];
#pragma unroll
        for (int i = 0; i < 4; i++)
#pragma unroll
            for (int j = 0; j < 4; j++) acc[i][j] *= cr[i];
#pragma unroll 8
        for (int kk = 0; kk < 64; kk++) {
            float p[4], v[4];
#pragma unroll
            for (int i = 0; i < 4; i++) p[i] = Ps[(ty * 4 + i) * PITCH + kk];
#pragma unroll
            for (int j = 0; j < 4; j++) v[j] = Vs[kk * PITCH + tx * 4 + j];
#pragma unroll
            for (int i = 0; i < 4; i++)
#pragma unroll
                for (int j = 0; j < 4; j++) acc[i][j] += p[i] * v[j];
        }
    }
    __syncthreads();

    float invl[4];
#pragma unroll
    for (int i = 0; i < 4; i++) invl[i] = 1.0f / rowL[ty * 4 + i];
#pragma unroll
    for (int i = 0; i < 4; i++) {
        size_t r = (size_t)b * SEQ + q0 + ty * 4 + i;
#pragma unroll
        for (int j = 0; j < 4; j++)
            out[r * DK + tx * 4 + j] = acc[i][j] * invl[i];
    }
}

// ---------------------------------------------------------------------------
extern "C" void kernel_launch(void* const* d_in, const int* in_sizes, int n_in,
                              void* d_out, int out_size)
{
    const float* q  = (const float*)d_in[0];
    const float* k  = (const float*)d_in[1];
    const float* v  = (const float*)d_in[2];
    const float* m  = (const float*)d_in[3];
    const float* Wq = (const float*)d_in[4];
    const float* bq = (const float*)d_in[5];
    const float* Wk = (const float*)d_in[6];
    const float* bk = (const float*)d_in[7];
    const float* Wv = (const float*)d_in[8];
    const float* bv = (const float*)d_in[9];
    float* out = (float*)d_out;

    // Projections (mask + 1/sqrt(dk) folded into q-hat)
    proj_kernel<<<ROWS / 64, 256>>>(q, Wq, bq, m, 0);
    proj_kernel<<<ROWS / 64, 256>>>(k, Wk, bk, nullptr, 1);
    proj_kernel<<<ROWS / 64, 256>>>(v, Wv, bv, nullptr, 2);

    // Attention (needs >48KB dynamic smem)
    cudaFuncSetAttribute(attn_kernel,
                         cudaFuncAttributeMaxDynamicSharedMemorySize,
                         ATTN_SMEM_BYTES);
    dim3 grid(SEQ / 64, BATCH);
    attn_kernel<<<grid, 256, ATTN_SMEM_BYTES>>>(out);
}

// round 3
// speedup vs baseline: 2.0498x; 2.0498x over previous
#include <cuda_runtime.h>
#include <cuda_fp16.h>
#include <cstdint>

// ============================================================================
// Problem constants
// ============================================================================
#define BATCH   4
#define SEQ     4096
#define DMODEL  1024
#define DK      64
#define ROWS    (BATCH * SEQ)        // 16384

// Projected tensors. q folded with mask*0.125. v split hi/lo for precision.
__device__ __half g_qh [ROWS * DK];
__device__ __half g_kh [ROWS * DK];
__device__ __half g_vhi[ROWS * DK];
__device__ __half g_vlo[ROWS * DK];

// ============================================================================
// small helpers
// ============================================================================
__device__ __forceinline__ uint32_t cvta_smem(const void* p) {
    return (uint32_t)__cvta_generic_to_shared(p);
}

#define LDSM_X4(r0, r1, r2, r3, addr) \
    asm volatile("ldmatrix.sync.aligned.m8n8.x4.shared.b16 {%0,%1,%2,%3}, [%4];" \
        : "=r"(r0), "=r"(r1), "=r"(r2), "=r"(r3) : "r"(addr))

#define LDSM_X4_T(r0, r1, r2, r3, addr) \
    asm volatile("ldmatrix.sync.aligned.m8n8.x4.trans.shared.b16 {%0,%1,%2,%3}, [%4];" \
        : "=r"(r0), "=r"(r1), "=r"(r2), "=r"(r3) : "r"(addr))

#define MMA16816(d, a, b0, b1) \
    asm volatile("mma.sync.aligned.m16n8k16.row.col.f32.f16.f16.f32 " \
        "{%0,%1,%2,%3}, {%4,%5,%6,%7}, {%8,%9}, {%0,%1,%2,%3};" \
        : "+f"((d)[0]), "+f"((d)[1]), "+f"((d)[2]), "+f"((d)[3]) \
        : "r"((a)[0]), "r"((a)[1]), "r"((a)[2]), "r"((a)[3]), "r"(b0), "r"(b1))

#define CP_ASYNC16(dst, src) \
    asm volatile("cp.async.cg.shared.global [%0], [%1], 16;" \
        :: "r"(dst), "l"(src) : "memory")
#define CP_COMMIT()  asm volatile("cp.async.commit_group;" ::: "memory")
#define CP_WAIT0()   asm volatile("cp.async.wait_group 0;" ::: "memory")
#define CP_WAIT1()   asm volatile("cp.async.wait_group 1;" ::: "memory")

__device__ __forceinline__ uint32_t pack_h2(float a, float b) {
    __half2 h = __floats2half2_rn(a, b);
    return *reinterpret_cast<uint32_t*>(&h);
}

// smem swizzle: row-major fp16 tiles, row = 128B = 8 chunks of 16B.
// addr(row, chunk) = row*128 + ((chunk ^ (row&7)) * 16)
__device__ __forceinline__ uint32_t sw_off(int row, int chunk) {
    return (uint32_t)(row * 128 + ((chunk ^ (row & 7)) << 4));
}

// ============================================================================
// Projection: Y = X @ W + b (fp32 compute) -> fp16 outputs.
//   which 0: g_qh = fp16((acc+b) * mask*0.125)
//   which 1: g_kh = fp16(acc+b)
//   which 2: g_vhi = fp16(v), g_vlo = fp16(v - float(g_vhi))
// 64x64 tile, 256 threads, transposed X tile -> float4 LDS.
// ============================================================================
#define PITCHP 68

__global__ __launch_bounds__(256) void proj_kernel(
    const float* __restrict__ X,
    const float* __restrict__ W,
    const float* __restrict__ bias,
    const float* __restrict__ mask,   // nullptr except q
    int which)
{
    __shared__ float XsT[64 * PITCHP];   // [kk][row]
    __shared__ float Ws [64 * PITCHP];   // [kk][col]

    const int tid  = threadIdx.x;
    const int row0 = blockIdx.x * 64;
    const int ty   = tid >> 4;
    const int tx   = tid & 15;

    float acc[4][4];
#pragma unroll
    for (int i = 0; i < 4; i++)
#pragma unroll
        for (int j = 0; j < 4; j++) acc[i][j] = 0.f;

    for (int k0 = 0; k0 < DMODEL; k0 += 64) {
        __syncthreads();
#pragma unroll
        for (int i = 0; i < 16; i++) {
            int idx = tid + i * 256;
            int r = idx >> 6, c = idx & 63;
            XsT[c * PITCHP + r] = X[(size_t)(row0 + r) * DMODEL + k0 + c];
            Ws [r * PITCHP + c] = W[(size_t)(k0 + r) * DK + c];
        }
        __syncthreads();
#pragma unroll 8
        for (int kk = 0; kk < 64; kk++) {
            float4 a  = *reinterpret_cast<const float4*>(&XsT[kk * PITCHP + ty * 4]);
            float4 bv = *reinterpret_cast<const float4*>(&Ws [kk * PITCHP + tx * 4]);
            float av[4] = {a.x, a.y, a.z, a.w};
            float bb[4] = {bv.x, bv.y, bv.z, bv.w};
#pragma unroll
            for (int i = 0; i < 4; i++)
#pragma unroll
                for (int j = 0; j < 4; j++) acc[i][j] += av[i] * bb[j];
        }
    }

#pragma unroll
    for (int i = 0; i < 4; i++) {
        int r = row0 + ty * 4 + i;
        float sc = (which == 0) ? (mask[r] * 0.125f) : 1.0f;
#pragma unroll
        for (int j = 0; j < 4; j++) {
            int c = tx * 4 + j;
            float val = (acc[i][j] + bias[c]) * sc;
            size_t o = (size_t)r * DK + c;
            if (which == 0) {
                g_qh[o] = __float2half_rn(val);
            } else if (which == 1) {
                g_kh[o] = __float2half_rn(val);
            } else {
                __half h = __float2half_rn(val);
                g_vhi[o] = h;
                g_vlo[o] = __float2half_rn(val - __half2float(h));
            }
        }
    }
}

// ============================================================================
// FlashAttention-2 style kernel with mma.sync.m16n8k16 (fp16 in, fp32 acc).
//   CTA: 128 threads (4 warps), Br=64 queries (16 rows/warp), Bc=64 keys/iter.
//   No-max softmax (logits bounded small); P kept in registers (FA2 layout
//   pairing: S accumulator fragments repack into PV A fragments).
//   PV in split precision: Phi*Vhi + Plo*Vhi + Phi*Vlo.
// ============================================================================
#define BR   64
#define BC   64
#define NKT  (SEQ / BC)          // 64

#define Q_BYTES     (BR * 128)           // 8192
#define TILE_BYTES  (BC * 128)           // 8192 per array
#define STAGE_BYTES (3 * TILE_BYTES)     // K, Vhi, Vlo = 24576
#define ATTN_SMEM   (Q_BYTES + 2 * STAGE_BYTES)   // 57344

__device__ __forceinline__ void prefetch_tile(char* stage, int b, int key0, int tid)
{
    const __half* srcs[3] = {g_kh, g_vhi, g_vlo};
#pragma unroll
    for (int i = 0; i < 12; i++) {
        int idx = tid + i * 128;          // 0..1535
        int arr = idx >> 9;               // 0..2
        int rem = idx & 511;
        int row = rem >> 3, c = rem & 7;
        const __half* g = srcs[arr] + ((size_t)b * SEQ + key0 + row) * DK + c * 8;
        uint32_t d = cvta_smem(stage + arr * TILE_BYTES) + sw_off(row, c);
        CP_ASYNC16(d, g);
    }
}

__global__ __launch_bounds__(128) void attn_kernel(float* __restrict__ out)
{
    extern __shared__ char smem[];
    char* Qs = smem;
    char* St = smem + Q_BYTES;

    const int tid  = threadIdx.x;
    const int lane = tid & 31;
    const int w    = tid >> 5;
    const int b    = blockIdx.y;
    const int q0   = blockIdx.x * BR;
    const int g    = lane >> 2;          // mma group row
    const int t    = lane & 3;           // mma group col
    const int qq   = lane >> 3;          // ldmatrix matrix id
    const int rr   = lane & 7;           // ldmatrix row-in-matrix

    // kick off tile 0 load first (overlaps with Q staging)
    prefetch_tile(St, b, 0, tid);
    CP_COMMIT();

    // stage Q tile (swizzled)
    {
        const __half* qb = g_qh + ((size_t)b * SEQ + q0) * DK;
#pragma unroll
        for (int i = 0; i < 4; i++) {
            int idx = tid + i * 128;      // 0..511
            int row = idx >> 3, c = idx & 7;
            uint4 v = *reinterpret_cast<const uint4*>(qb + (size_t)row * DK + c * 8);
            *reinterpret_cast<uint4*>(Qs + sw_off(row, c)) = v;
        }
    }
    __syncthreads();

    // Q A-fragments: 4 k-steps (k=16 each over DK=64)
    uint32_t qA[4][4];
    {
        uint32_t qbase = cvta_smem(Qs);
        int row = w * 16 + (qq & 1) * 8 + rr;
#pragma unroll
        for (int s = 0; s < 4; s++) {
            uint32_t addr = qbase + sw_off(row, 2 * s + (qq >> 1));
            LDSM_X4(qA[s][0], qA[s][1], qA[s][2], qA[s][3], addr);
        }
    }

    float O[8][4];
#pragma unroll
    for (int j = 0; j < 8; j++)
#pragma unroll
        for (int i = 0; i < 4; i++) O[j][i] = 0.f;
    float L0 = 0.f, L1 = 0.f;

    for (int kt = 0; kt < NKT; kt++) {
        const int s = kt & 1;
        char* stage = St + s * STAGE_BYTES;

        if (kt + 1 < NKT) {
            prefetch_tile(St + (s ^ 1) * STAGE_BYTES, b, (kt + 1) * BC, tid);
            CP_COMMIT();
            CP_WAIT1();       // tile kt complete; kt+1 still in flight
        } else {
            CP_WAIT0();
        }
        __syncthreads();

        const uint32_t kb  = cvta_smem(stage);
        const uint32_t vhb = kb + TILE_BYTES;
        const uint32_t vlb = kb + 2 * TILE_BYTES;

        // ---- S = Q @ K^T, then exp -> P fragments (hi/lo split) ----
        uint32_t aPhi[4][4], aPlo[4][4];
#pragma unroll
        for (int j = 0; j < 8; j++) {
            float d[4] = {0.f, 0.f, 0.f, 0.f};
#pragma unroll
            for (int sp = 0; sp < 2; sp++) {
                int row = j * 8 + rr;                        // key row
                uint32_t addr = kb + sw_off(row, 4 * sp + qq);
                uint32_t k0, k1, k2, k3;
                LDSM_X4(k0, k1, k2, k3, addr);
                MMA16816(d, qA[2 * sp],     k0, k1);
                MMA16816(d, qA[2 * sp + 1], k2, k3);
            }
            float p0 = __expf(d[0]), p1 = __expf(d[1]);
            float p2 = __expf(d[2]), p3 = __expf(d[3]);
            L0 += p0 + p1;
            L1 += p2 + p3;
            __half h0 = __float2half_rn(p0), h1 = __float2half_rn(p1);
            __half h2 = __float2half_rn(p2), h3 = __float2half_rn(p3);
            __half2 hA = __halves2half2(h0, h1);
            __half2 hB = __halves2half2(h2, h3);
            int sp2 = j >> 1, o = (j & 1) * 2;
            aPhi[sp2][o]     = *reinterpret_cast<uint32_t*>(&hA);
            aPhi[sp2][o + 1] = *reinterpret_cast<uint32_t*>(&hB);
            aPlo[sp2][o]     = pack_h2(p0 - __half2float(h0), p1 - __half2float(h1));
            aPlo[sp2][o + 1] = pack_h2(p2 - __half2float(h2), p3 - __half2float(h3));
        }

        // ---- O += Phi@Vhi + Plo@Vhi + Phi@Vlo ----
#pragma unroll
        for (int j = 0; j < 8; j++) {
#pragma unroll
            for (int sp = 0; sp < 2; sp++) {
                int row = 32 * sp + qq * 8 + rr;             // key row
                uint32_t v0, v1, v2, v3, u0, u1, u2, u3;
                LDSM_X4_T(v0, v1, v2, v3, vhb + sw_off(row, j));
                MMA16816(O[j], aPhi[2 * sp],     v0, v1);
                MMA16816(O[j], aPhi[2 * sp + 1], v2, v3);
                MMA16816(O[j], aPlo[2 * sp],     v0, v1);
                MMA16816(O[j], aPlo[2 * sp + 1], v2, v3);
                LDSM_X4_T(u0, u1, u2, u3, vlb + sw_off(row, j));
                MMA16816(O[j], aPhi[2 * sp],     u0, u1);
                MMA16816(O[j], aPhi[2 * sp + 1], u2, u3);
            }
        }
        __syncthreads();   // all warps done reading stage s before it is refilled
    }

    // ---- epilogue: row-sum reduce over quad, divide, store ----
    L0 += __shfl_xor_sync(0xffffffffu, L0, 1);
    L0 += __shfl_xor_sync(0xffffffffu, L0, 2);
    L1 += __shfl_xor_sync(0xffffffffu, L1, 1);
    L1 += __shfl_xor_sync(0xffffffffu, L1, 2);
    const float i0 = 1.0f / L0;
    const float i1 = 1.0f / L1;

    const size_t row_a = (size_t)b * SEQ + q0 + w * 16 + g;
    const size_t row_b = row_a + 8;
#pragma unroll
    for (int j = 0; j < 8; j++) {
        int col = 8 * j + 2 * t;
        float2 va = make_float2(O[j][0] * i0, O[j][1] * i0);
        float2 vb = make_float2(O[j][2] * i1, O[j][3] * i1);
        *reinterpret_cast<float2*>(out + row_a * DK + col) = va;
        *reinterpret_cast<float2*>(out + row_b * DK + col) = vb;
    }
}

// ============================================================================
extern "C" void kernel_launch(void* const* d_in, const int* in_sizes, int n_in,
                              void* d_out, int out_size)
{
    const float* q  = (const float*)d_in[0];
    const float* k  = (const float*)d_in[1];
    const float* v  = (const float*)d_in[2];
    const float* m  = (const float*)d_in[3];
    const float* Wq = (const float*)d_in[4];
    const float* bq = (const float*)d_in[5];
    const float* Wk = (const float*)d_in[6];
    const float* bk = (const float*)d_in[7];
    const float* Wv = (const float*)d_in[8];
    const float* bv = (const float*)d_in[9];
    float* out = (float*)d_out;

    proj_kernel<<<ROWS / 64, 256>>>(q, Wq, bq, m, 0);
    proj_kernel<<<ROWS / 64, 256>>>(k, Wk, bk, nullptr, 1);
    proj_kernel<<<ROWS / 64, 256>>>(v, Wv, bv, nullptr, 2);

    cudaFuncSetAttribute(attn_kernel,
                         cudaFuncAttributeMaxDynamicSharedMemorySize,
                         ATTN_SMEM);
    dim3 grid(SEQ / BR, BATCH);
    attn_kernel<<<grid, 128, ATTN_SMEM>>>(out);
}

// round 4
// speedup vs baseline: 3.8832x; 1.8945x over previous
#include <cuda_runtime.h>
#include <cuda_fp16.h>
#include <cstdint>

// ============================================================================
// Problem constants
// ============================================================================
#define BATCH   4
#define SEQ     4096
#define DMODEL  1024
#define DK      64
#define ROWS    (BATCH * SEQ)        // 16384

// Projected tensors. q folded with mask*0.125. v split hi/lo for precision.
__device__ __half g_qh [ROWS * DK];
__device__ __half g_kh [ROWS * DK];
__device__ __half g_vhi[ROWS * DK];
__device__ __half g_vlo[ROWS * DK];

// split-K attention scratch: two halves write disjoint buffers (deterministic)
__device__ float g_Oacc[2][ROWS * DK];
__device__ float g_Lacc[2][ROWS];

// ============================================================================
// small helpers
// ============================================================================
__device__ __forceinline__ uint32_t cvta_smem(const void* p) {
    return (uint32_t)__cvta_generic_to_shared(p);
}

#define LDSM_X4(r0, r1, r2, r3, addr) \
    asm volatile("ldmatrix.sync.aligned.m8n8.x4.shared.b16 {%0,%1,%2,%3}, [%4];" \
        : "=r"(r0), "=r"(r1), "=r"(r2), "=r"(r3) : "r"(addr))

#define LDSM_X4_T(r0, r1, r2, r3, addr) \
    asm volatile("ldmatrix.sync.aligned.m8n8.x4.trans.shared.b16 {%0,%1,%2,%3}, [%4];" \
        : "=r"(r0), "=r"(r1), "=r"(r2), "=r"(r3) : "r"(addr))

#define MMA16816(d, a, b0, b1) \
    asm volatile("mma.sync.aligned.m16n8k16.row.col.f32.f16.f16.f32 " \
        "{%0,%1,%2,%3}, {%4,%5,%6,%7}, {%8,%9}, {%0,%1,%2,%3};" \
        : "+f"((d)[0]), "+f"((d)[1]), "+f"((d)[2]), "+f"((d)[3]) \
        : "r"((a)[0]), "r"((a)[1]), "r"((a)[2]), "r"((a)[3]), "r"(b0), "r"(b1))

#define CP_ASYNC16(dst, src) \
    asm volatile("cp.async.cg.shared.global [%0], [%1], 16;" \
        :: "r"(dst), "l"(src) : "memory")
#define CP_COMMIT()  asm volatile("cp.async.commit_group;" ::: "memory")
#define CP_WAIT0()   asm volatile("cp.async.wait_group 0;" ::: "memory")
#define CP_WAIT1()   asm volatile("cp.async.wait_group 1;" ::: "memory")

__device__ __forceinline__ uint32_t pack_h2(float a, float b) {
    __half2 h = __floats2half2_rn(a, b);
    return *reinterpret_cast<uint32_t*>(&h);
}

// smem swizzle: row-major fp16 tiles, row = 128B = 8 chunks of 16B.
__device__ __forceinline__ uint32_t sw_off(int row, int chunk) {
    return (uint32_t)(row * 128 + ((chunk ^ (row & 7)) << 4));
}

// ============================================================================
// Tensor-core projection: Y = X @ W + b  via split-fp16 (3-MMA trick).
//   CTA: 128 threads (4 warps), 64 rows x 64 cols output, K chunks of 64.
//   blockIdx.y selects which projection (0=q with mask fold, 1=k, 2=v split).
//   A-frag pattern == R3 Q load; B-frag pattern == R3 V trans load (verified).
// ============================================================================
#define PJ_BR 64
#define PJ_KC 64
#define PJ_TILE_BYTES (64 * 128)   // 8KB per fp16 tile

__global__ __launch_bounds__(128) void proj_mma_kernel(
    const float* __restrict__ Xq, const float* __restrict__ Xk,
    const float* __restrict__ Xv,
    const float* __restrict__ Wq, const float* __restrict__ bq,
    const float* __restrict__ Wk, const float* __restrict__ bk,
    const float* __restrict__ Wv, const float* __restrict__ bv,
    const float* __restrict__ mask)
{
    __shared__ __align__(16) char sXhi[PJ_TILE_BYTES];
    __shared__ __align__(16) char sXlo[PJ_TILE_BYTES];
    __shared__ __align__(16) char sWhi[PJ_TILE_BYTES];
    __shared__ __align__(16) char sWlo[PJ_TILE_BYTES];

    const int tid   = threadIdx.x;
    const int lane  = tid & 31;
    const int w     = tid >> 5;
    const int which = blockIdx.y;
    const int row0  = blockIdx.x * PJ_BR;
    const int g     = lane >> 2;
    const int t     = lane & 3;
    const int qq    = lane >> 3;
    const int rr    = lane & 7;

    const float* X    = (which == 0) ? Xq : (which == 1) ? Xk : Xv;
    const float* W    = (which == 0) ? Wq : (which == 1) ? Wk : Wv;
    const float* bias = (which == 0) ? bq : (which == 1) ? bk : bv;

    float O[8][4];
#pragma unroll
    for (int j = 0; j < 8; j++)
#pragma unroll
        for (int i = 0; i < 4; i++) O[j][i] = 0.f;

    const uint32_t xhiB = cvta_smem(sXhi), xloB = cvta_smem(sXlo);
    const uint32_t whiB = cvta_smem(sWhi), wloB = cvta_smem(sWlo);

    for (int k0 = 0; k0 < DMODEL; k0 += PJ_KC) {
        __syncthreads();
        // ---- stage X[64 rows x 64 k] fp32 -> hi/lo fp16 swizzled ----
#pragma unroll
        for (int i = 0; i < 4; i++) {
            int u = tid + i * 128;          // 0..511 units of 8 floats
            int r = u >> 3, c = u & 7;
            const float* src = X + (size_t)(row0 + r) * DMODEL + k0 + c * 8;
            float4 a = *reinterpret_cast<const float4*>(src);
            float4 b = *reinterpret_cast<const float4*>(src + 4);
            __half h[8];
            h[0]=__float2half_rn(a.x); h[1]=__float2half_rn(a.y);
            h[2]=__float2half_rn(a.z); h[3]=__float2half_rn(a.w);
            h[4]=__float2half_rn(b.x); h[5]=__float2half_rn(b.y);
            h[6]=__float2half_rn(b.z); h[7]=__float2half_rn(b.w);
            uint4 hv, lv;
            hv.x = pack_h2(__half2float(h[0]), __half2float(h[1]));
            hv.y = pack_h2(__half2float(h[2]), __half2float(h[3]));
            hv.z = pack_h2(__half2float(h[4]), __half2float(h[5]));
            hv.w = pack_h2(__half2float(h[6]), __half2float(h[7]));
            lv.x = pack_h2(a.x - __half2float(h[0]), a.y - __half2float(h[1]));
            lv.y = pack_h2(a.z - __half2float(h[2]), a.w - __half2float(h[3]));
            lv.z = pack_h2(b.x - __half2float(h[4]), b.y - __half2float(h[5]));
            lv.w = pack_h2(b.z - __half2float(h[6]), b.w - __half2float(h[7]));
            *reinterpret_cast<uint4*>(sXhi + sw_off(r, c)) = hv;
            *reinterpret_cast<uint4*>(sXlo + sw_off(r, c)) = lv;
        }
        // ---- stage W[64 k x 64 n] fp32 -> hi/lo fp16 swizzled ----
#pragma unroll
        for (int i = 0; i < 4; i++) {
            int u = tid + i * 128;
            int r = u >> 3, c = u & 7;
            const float* src = W + (size_t)(k0 + r) * DK + c * 8;
            float4 a = *reinterpret_cast<const float4*>(src);
            float4 b = *reinterpret_cast<const float4*>(src + 4);
            __half h[8];
            h[0]=__float2half_rn(a.x); h[1]=__float2half_rn(a.y);
            h[2]=__float2half_rn(a.z); h[3]=__float2half_rn(a.w);
            h[4]=__float2half_rn(b.x); h[5]=__float2half_rn(b.y);
            h[6]=__float2half_rn(b.z); h[7]=__float2half_rn(b.w);
            uint4 hv, lv;
            hv.x = pack_h2(__half2float(h[0]), __half2float(h[1]));
            hv.y = pack_h2(__half2float(h[2]), __half2float(h[3]));
            hv.z = pack_h2(__half2float(h[4]), __half2float(h[5]));
            hv.w = pack_h2(__half2float(h[6]), __half2float(h[7]));
            lv.x = pack_h2(a.x - __half2float(h[0]), a.y - __half2float(h[1]));
            lv.y = pack_h2(a.z - __half2float(h[2]), a.w - __half2float(h[3]));
            lv.z = pack_h2(b.x - __half2float(h[4]), b.y - __half2float(h[5]));
            lv.w = pack_h2(b.z - __half2float(h[6]), b.w - __half2float(h[7]));
            *reinterpret_cast<uint4*>(sWhi + sw_off(r, c)) = hv;
            *reinterpret_cast<uint4*>(sWlo + sw_off(r, c)) = lv;
        }
        __syncthreads();

        // ---- A fragments (rows = warp's 16), 4 k-steps, hi and lo ----
        uint32_t aHi[4][4], aLo[4][4];
        {
            int arow = w * 16 + (qq & 1) * 8 + rr;
#pragma unroll
            for (int s = 0; s < 4; s++) {
                uint32_t off = sw_off(arow, 2 * s + (qq >> 1));
                LDSM_X4(aHi[s][0], aHi[s][1], aHi[s][2], aHi[s][3], xhiB + off);
                LDSM_X4(aLo[s][0], aLo[s][1], aLo[s][2], aLo[s][3], xloB + off);
            }
        }
        // ---- B fragments + MMAs: hi*hi + lo*hi + hi*lo ----
        int brow_base = qq * 8 + rr;
#pragma unroll
        for (int j = 0; j < 8; j++) {
#pragma unroll
            for (int sp = 0; sp < 2; sp++) {
                int brow = 32 * sp + brow_base;
                uint32_t v0, v1, v2, v3, u0, u1, u2, u3;
                LDSM_X4_T(v0, v1, v2, v3, whiB + sw_off(brow, j));
                MMA16816(O[j], aHi[2 * sp],     v0, v1);
                MMA16816(O[j], aHi[2 * sp + 1], v2, v3);
                MMA16816(O[j], aLo[2 * sp],     v0, v1);
                MMA16816(O[j], aLo[2 * sp + 1], v2, v3);
                LDSM_X4_T(u0, u1, u2, u3, wloB + sw_off(brow, j));
                MMA16816(O[j], aHi[2 * sp],     u0, u1);
                MMA16816(O[j], aHi[2 * sp + 1], u2, u3);
            }
        }
    }

    // ---- epilogue: +bias, (mask*0.125 for q), emit fp16 (v: hi/lo split) ----
    const int row_a = row0 + w * 16 + g;
    const int row_b = row_a + 8;
    const float sca = (which == 0) ? (mask[row_a] * 0.125f) : 1.0f;
    const float scb = (which == 0) ? (mask[row_b] * 0.125f) : 1.0f;
#pragma unroll
    for (int j = 0; j < 8; j++) {
        int col = 8 * j + 2 * t;
        float b0 = bias[col], b1 = bias[col + 1];
        float va0 = (O[j][0] + b0) * sca, va1 = (O[j][1] + b1) * sca;
        float vb0 = (O[j][2] + b0) * scb, vb1 = (O[j][3] + b1) * scb;
        size_t oa = (size_t)row_a * DK + col;
        size_t ob = (size_t)row_b * DK + col;
        if (which == 0) {
            *reinterpret_cast<uint32_t*>(&g_qh[oa]) = pack_h2(va0, va1);
            *reinterpret_cast<uint32_t*>(&g_qh[ob]) = pack_h2(vb0, vb1);
        } else if (which == 1) {
            *reinterpret_cast<uint32_t*>(&g_kh[oa]) = pack_h2(va0, va1);
            *reinterpret_cast<uint32_t*>(&g_kh[ob]) = pack_h2(vb0, vb1);
        } else {
            __half ha0 = __float2half_rn(va0), ha1 = __float2half_rn(va1);
            __half hb0 = __float2half_rn(vb0), hb1 = __float2half_rn(vb1);
            *reinterpret_cast<uint32_t*>(&g_vhi[oa]) =
                pack_h2(__half2float(ha0), __half2float(ha1));
            *reinterpret_cast<uint32_t*>(&g_vhi[ob]) =
                pack_h2(__half2float(hb0), __half2float(hb1));
            *reinterpret_cast<uint32_t*>(&g_vlo[oa]) =
                pack_h2(va0 - __half2float(ha0), va1 - __half2float(ha1));
            *reinterpret_cast<uint32_t*>(&g_vlo[ob]) =
                pack_h2(vb0 - __half2float(hb0), vb1 - __half2float(hb1));
        }
    }
}

// ============================================================================
// FlashAttention (fp16 mma.sync), split-K over gridDim.z=2.
//   Each half accumulates (O, L) into its own scratch; normalize combines.
//   No-max softmax is linear in exp() so halves sum exactly.
// ============================================================================
#define BR   64
#define BC   64
#define NKT_HALF (SEQ / BC / 2)      // 32 tiles per half

#define Q_BYTES     (BR * 128)
#define TILE_BYTES  (BC * 128)
#define STAGE_BYTES (3 * TILE_BYTES)
#define ATTN_SMEM   (Q_BYTES + 2 * STAGE_BYTES)   // 57344

__device__ __forceinline__ void prefetch_tile(char* stage, int b, int key0, int tid)
{
    const __half* srcs[3] = {g_kh, g_vhi, g_vlo};
#pragma unroll
    for (int i = 0; i < 12; i++) {
        int idx = tid + i * 128;
        int arr = idx >> 9;
        int rem = idx & 511;
        int row = rem >> 3, c = rem & 7;
        const __half* g = srcs[arr] + ((size_t)b * SEQ + key0 + row) * DK + c * 8;
        uint32_t d = cvta_smem(stage + arr * TILE_BYTES) + sw_off(row, c);
        CP_ASYNC16(d, g);
    }
}

__global__ __launch_bounds__(128) void attn_kernel()
{
    extern __shared__ char smem[];
    char* Qs = smem;
    char* St = smem + Q_BYTES;

    const int tid  = threadIdx.x;
    const int lane = tid & 31;
    const int w    = tid >> 5;
    const int b    = blockIdx.y;
    const int q0   = blockIdx.x * BR;
    const int z    = blockIdx.z;
    const int key_base = z * (SEQ / 2);
    const int g    = lane >> 2;
    const int t    = lane & 3;
    const int qq   = lane >> 3;
    const int rr   = lane & 7;

    prefetch_tile(St, b, key_base, tid);
    CP_COMMIT();

    {
        const __half* qb = g_qh + ((size_t)b * SEQ + q0) * DK;
#pragma unroll
        for (int i = 0; i < 4; i++) {
            int idx = tid + i * 128;
            int row = idx >> 3, c = idx & 7;
            uint4 v = *reinterpret_cast<const uint4*>(qb + (size_t)row * DK + c * 8);
            *reinterpret_cast<uint4*>(Qs + sw_off(row, c)) = v;
        }
    }
    __syncthreads();

    uint32_t qA[4][4];
    {
        uint32_t qbase = cvta_smem(Qs);
        int row = w * 16 + (qq & 1) * 8 + rr;
#pragma unroll
        for (int s = 0; s < 4; s++) {
            uint32_t addr = qbase + sw_off(row, 2 * s + (qq >> 1));
            LDSM_X4(qA[s][0], qA[s][1], qA[s][2], qA[s][3], addr);
        }
    }

    float O[8][4];
#pragma unroll
    for (int j = 0; j < 8; j++)
#pragma unroll
        for (int i = 0; i < 4; i++) O[j][i] = 0.f;
    float L0 = 0.f, L1 = 0.f;

    for (int kt = 0; kt < NKT_HALF; kt++) {
        const int s = kt & 1;
        char* stage = St + s * STAGE_BYTES;

        if (kt + 1 < NKT_HALF) {
            prefetch_tile(St + (s ^ 1) * STAGE_BYTES, b,
                          key_base + (kt + 1) * BC, tid);
            CP_COMMIT();
            CP_WAIT1();
        } else {
            CP_WAIT0();
        }
        __syncthreads();

        const uint32_t kb  = cvta_smem(stage);
        const uint32_t vhb = kb + TILE_BYTES;
        const uint32_t vlb = kb + 2 * TILE_BYTES;

        uint32_t aPhi[4][4], aPlo[4][4];
#pragma unroll
        for (int j = 0; j < 8; j++) {
            float d[4] = {0.f, 0.f, 0.f, 0.f};
#pragma unroll
            for (int sp = 0; sp < 2; sp++) {
                int row = j * 8 + rr;
                uint32_t addr = kb + sw_off(row, 4 * sp + qq);
                uint32_t k0, k1, k2, k3;
                LDSM_X4(k0, k1, k2, k3, addr);
                MMA16816(d, qA[2 * sp],     k0, k1);
                MMA16816(d, qA[2 * sp + 1], k2, k3);
            }
            float p0 = __expf(d[0]), p1 = __expf(d[1]);
            float p2 = __expf(d[2]), p3 = __expf(d[3]);
            L0 += p0 + p1;
            L1 += p2 + p3;
            __half h0 = __float2half_rn(p0), h1 = __float2half_rn(p1);
            __half h2 = __float2half_rn(p2), h3 = __float2half_rn(p3);
            __half2 hA = __halves2half2(h0, h1);
            __half2 hB = __halves2half2(h2, h3);
            int sp2 = j >> 1, o = (j & 1) * 2;
            aPhi[sp2][o]     = *reinterpret_cast<uint32_t*>(&hA);
            aPhi[sp2][o + 1] = *reinterpret_cast<uint32_t*>(&hB);
            aPlo[sp2][o]     = pack_h2(p0 - __half2float(h0), p1 - __half2float(h1));
            aPlo[sp2][o + 1] = pack_h2(p2 - __half2float(h2), p3 - __half2float(h3));
        }

#pragma unroll
        for (int j = 0; j < 8; j++) {
#pragma unroll
            for (int sp = 0; sp < 2; sp++) {
                int row = 32 * sp + qq * 8 + rr;
                uint32_t v0, v1, v2, v3, u0, u1, u2, u3;
                LDSM_X4_T(v0, v1, v2, v3, vhb + sw_off(row, j));
                MMA16816(O[j], aPhi[2 * sp],     v0, v1);
                MMA16816(O[j], aPhi[2 * sp + 1], v2, v3);
                MMA16816(O[j], aPlo[2 * sp],     v0, v1);
                MMA16816(O[j], aPlo[2 * sp + 1], v2, v3);
                LDSM_X4_T(u0, u1, u2, u3, vlb + sw_off(row, j));
                MMA16816(O[j], aPhi[2 * sp],     u0, u1);
                MMA16816(O[j], aPhi[2 * sp + 1], u2, u3);
            }
        }
        __syncthreads();
    }

    // ---- epilogue: partial (O, L) to this half's scratch ----
    L0 += __shfl_xor_sync(0xffffffffu, L0, 1);
    L0 += __shfl_xor_sync(0xffffffffu, L0, 2);
    L1 += __shfl_xor_sync(0xffffffffu, L1, 1);
    L1 += __shfl_xor_sync(0xffffffffu, L1, 2);

    const size_t row_a = (size_t)b * SEQ + q0 + w * 16 + g;
    const size_t row_b = row_a + 8;
    float* Oz = g_Oacc[z];
    if (t == 0) {
        g_Lacc[z][row_a] = L0;
        g_Lacc[z][row_b] = L1;
    }
#pragma unroll
    for (int j = 0; j < 8; j++) {
        int col = 8 * j + 2 * t;
        *reinterpret_cast<float2*>(Oz + row_a * DK + col) =
            make_float2(O[j][0], O[j][1]);
        *reinterpret_cast<float2*>(Oz + row_b * DK + col) =
            make_float2(O[j][2], O[j][3]);
    }
}

// ============================================================================
// Normalize: out = (Oa + Ob) / (La + Lb)
// ============================================================================
__global__ __launch_bounds__(256) void normalize_kernel(float* __restrict__ out)
{
    int i = blockIdx.x * 256 + threadIdx.x;      // float4 index
    int row = i >> 4;
    float inv = 1.0f / (g_Lacc[0][row] + g_Lacc[1][row]);
    float4 a = *reinterpret_cast<const float4*>(&g_Oacc[0][(size_t)i * 4]);
    float4 c = *reinterpret_cast<const float4*>(&g_Oacc[1][(size_t)i * 4]);
    float4 r;
    r.x = (a.x + c.x) * inv;
    r.y = (a.y + c.y) * inv;
    r.z = (a.z + c.z) * inv;
    r.w = (a.w + c.w) * inv;
    *reinterpret_cast<float4*>(out + (size_t)i * 4) = r;
}

// ============================================================================
extern "C" void kernel_launch(void* const* d_in, const int* in_sizes, int n_in,
                              void* d_out, int out_size)
{
    const float* q  = (const float*)d_in[0];
    const float* k  = (const float*)d_in[1];
    const float* v  = (const float*)d_in[2];
    const float* m  = (const float*)d_in[3];
    const float* Wq = (const float*)d_in[4];
    const float* bq = (const float*)d_in[5];
    const float* Wk = (const float*)d_in[6];
    const float* bk = (const float*)d_in[7];
    const float* Wv = (const float*)d_in[8];
    const float* bv = (const float*)d_in[9];
    float* out = (float*)d_out;

    dim3 pgrid(ROWS / PJ_BR, 3);
    proj_mma_kernel<<<pgrid, 128>>>(q, k, v, Wq, bq, Wk, bk, Wv, bv, m);

    cudaFuncSetAttribute(attn_kernel,
                         cudaFuncAttributeMaxDynamicSharedMemorySize,
                         ATTN_SMEM);
    dim3 grid(SEQ / BR, BATCH, 2);
    attn_kernel<<<grid, 128, ATTN_SMEM>>>();

    normalize_kernel<<<ROWS * DK / 4 / 256, 256>>>(out);
}

// round 5
// speedup vs baseline: 5.3390x; 1.3749x over previous
#include <cuda_runtime.h>
#include <cuda_fp16.h>
#include <cstdint>

// ============================================================================
// Problem constants
// ============================================================================
#define BATCH   4
#define SEQ     4096
#define DMODEL  1024
#define DK      64
#define ROWS    (BATCH * SEQ)        // 16384

// Projected tensors. q folded with mask*0.125. v split hi/lo for precision.
__device__ __align__(16) __half g_qh [ROWS * DK];
__device__ __align__(16) __half g_kh [ROWS * DK];
__device__ __align__(16) __half g_vhi[ROWS * DK];
__device__ __align__(16) __half g_vlo[ROWS * DK];

// Pre-converted weights (hi/lo fp16), 3 projections flat
__device__ __align__(16) __half g_Whi[3 * DMODEL * DK];
__device__ __align__(16) __half g_Wlo[3 * DMODEL * DK];

// split-K attention scratch: 4 quarters write disjoint buffers (deterministic)
#define ZSPLIT 4
__device__ float g_Oacc[ZSPLIT][ROWS * DK];
__device__ float g_Lacc[ZSPLIT][ROWS];

// ============================================================================
// small helpers
// ============================================================================
__device__ __forceinline__ uint32_t cvta_smem(const void* p) {
    return (uint32_t)__cvta_generic_to_shared(p);
}

#define LDSM_X4(r0, r1, r2, r3, addr) \
    asm volatile("ldmatrix.sync.aligned.m8n8.x4.shared.b16 {%0,%1,%2,%3}, [%4];" \
        : "=r"(r0), "=r"(r1), "=r"(r2), "=r"(r3) : "r"(addr))

#define LDSM_X4_T(r0, r1, r2, r3, addr) \
    asm volatile("ldmatrix.sync.aligned.m8n8.x4.trans.shared.b16 {%0,%1,%2,%3}, [%4];" \
        : "=r"(r0), "=r"(r1), "=r"(r2), "=r"(r3) : "r"(addr))

#define MMA16816(d, a, b0, b1) \
    asm volatile("mma.sync.aligned.m16n8k16.row.col.f32.f16.f16.f32 " \
        "{%0,%1,%2,%3}, {%4,%5,%6,%7}, {%8,%9}, {%0,%1,%2,%3};" \
        : "+f"((d)[0]), "+f"((d)[1]), "+f"((d)[2]), "+f"((d)[3]) \
        : "r"((a)[0]), "r"((a)[1]), "r"((a)[2]), "r"((a)[3]), "r"(b0), "r"(b1))

#define CP_ASYNC16(dst, src) \
    asm volatile("cp.async.cg.shared.global [%0], [%1], 16;" \
        :: "r"(dst), "l"(src) : "memory")
#define CP_COMMIT()  asm volatile("cp.async.commit_group;" ::: "memory")
#define CP_WAIT0()   asm volatile("cp.async.wait_group 0;" ::: "memory")
#define CP_WAIT1()   asm volatile("cp.async.wait_group 1;" ::: "memory")

__device__ __forceinline__ uint32_t pack_h2(float a, float b) {
    __half2 h = __floats2half2_rn(a, b);
    return *reinterpret_cast<uint32_t*>(&h);
}

// smem swizzle: row-major fp16 tiles, row = 128B = 8 chunks of 16B.
__device__ __forceinline__ uint32_t sw_off(int row, int chunk) {
    return (uint32_t)(row * 128 + ((chunk ^ (row & 7)) << 4));
}

// ============================================================================
// Weight pre-conversion: fp32 -> fp16 hi + lo residual, once.
// ============================================================================
__global__ __launch_bounds__(256) void wconv_kernel(
    const float* __restrict__ Wq, const float* __restrict__ Wk,
    const float* __restrict__ Wv)
{
    int i = blockIdx.x * 256 + threadIdx.x;          // 0..65535
    int which = blockIdx.y;
    const float* W = (which == 0) ? Wq : (which == 1) ? Wk : Wv;
    float v = W[i];
    __half h = __float2half_rn(v);
    g_Whi[which * DMODEL * DK + i] = h;
    g_Wlo[which * DMODEL * DK + i] = __float2half_rn(v - __half2float(h));
}

// ============================================================================
// Tensor-core projection (split-fp16 3-MMA), software-pipelined:
//   - X fp32 prefetched into registers one chunk ahead (LDG hides under MMA)
//   - W hi/lo tiles cp.async'd from pre-converted global (no convert)
//   - double-buffered smem, ONE __syncthreads per chunk
// CTA: 128 threads, 64 rows x 64 cols output, 16 K-chunks of 64.
// ============================================================================
#define PJ_TILE 8192                      // one 64x128B fp16 tile
#define PJ_SMEM (8 * PJ_TILE)             // Xhi2, Xlo2, Whi2, Wlo2 = 64KB
#define OFF_XHI(s) ((s) * PJ_TILE)
#define OFF_XLO(s) (16384 + (s) * PJ_TILE)
#define OFF_WHI(s) (32768 + (s) * PJ_TILE)
#define OFF_WLO(s) (49152 + (s) * PJ_TILE)

__global__ __launch_bounds__(128) void proj_mma_kernel(
    const float* __restrict__ Xq, const float* __restrict__ Xk,
    const float* __restrict__ Xv,
    const float* __restrict__ bq, const float* __restrict__ bk,
    const float* __restrict__ bv,
    const float* __restrict__ mask)
{
    extern __shared__ __align__(16) char psm[];
    const uint32_t sbase = cvta_smem(psm);

    const int tid   = threadIdx.x;
    const int lane  = tid & 31;
    const int w     = tid >> 5;
    const int which = blockIdx.y;
    const int row0  = blockIdx.x * 64;
    const int g     = lane >> 2;
    const int t     = lane & 3;
    const int qq    = lane >> 3;
    const int rr    = lane & 7;

    const float* X    = (which == 0) ? Xq : (which == 1) ? Xk : Xv;
    const float* bias = (which == 0) ? bq : (which == 1) ? bk : bv;
    const __half* Whi = g_Whi + which * DMODEL * DK;
    const __half* Wlo = g_Wlo + which * DMODEL * DK;

    // this thread's staging coordinates (4 units of 8 floats each)
    const int sr[4] = { (tid) >> 3, (tid + 128) >> 3, (tid + 256) >> 3, (tid + 384) >> 3 };
    const int sc    = tid & 7;

    float O[8][4];
#pragma unroll
    for (int j = 0; j < 8; j++)
#pragma unroll
        for (int i = 0; i < 4; i++) O[j][i] = 0.f;

    // prefetch chunk 0 X into registers
    float4 xa[4], xb[4];
#pragma unroll
    for (int i = 0; i < 4; i++) {
        const float* src = X + (size_t)(row0 + sr[i]) * DMODEL + sc * 8;
        xa[i] = *reinterpret_cast<const float4*>(src);
        xb[i] = *reinterpret_cast<const float4*>(src + 4);
    }

    for (int kc = 0; kc < DMODEL / 64; kc++) {
        const int s = kc & 1;
        const int k0 = kc * 64;

        // ---- convert X regs -> swizzled hi/lo fp16 smem ----
#pragma unroll
        for (int i = 0; i < 4; i++) {
            float4 a = xa[i], b = xb[i];
            __half h[8];
            h[0]=__float2half_rn(a.x); h[1]=__float2half_rn(a.y);
            h[2]=__float2half_rn(a.z); h[3]=__float2half_rn(a.w);
            h[4]=__float2half_rn(b.x); h[5]=__float2half_rn(b.y);
            h[6]=__float2half_rn(b.z); h[7]=__float2half_rn(b.w);
            uint4 hv, lv;
            hv.x = pack_h2(__half2float(h[0]), __half2float(h[1]));
            hv.y = pack_h2(__half2float(h[2]), __half2float(h[3]));
            hv.z = pack_h2(__half2float(h[4]), __half2float(h[5]));
            hv.w = pack_h2(__half2float(h[6]), __half2float(h[7]));
            lv.x = pack_h2(a.x - __half2float(h[0]), a.y - __half2float(h[1]));
            lv.y = pack_h2(a.z - __half2float(h[2]), a.w - __half2float(h[3]));
            lv.z = pack_h2(b.x - __half2float(h[4]), b.y - __half2float(h[5]));
            lv.w = pack_h2(b.z - __half2float(h[6]), b.w - __half2float(h[7]));
            uint32_t so = sw_off(sr[i], sc);
            *reinterpret_cast<uint4*>(psm + OFF_XHI(s) + so) = hv;
            *reinterpret_cast<uint4*>(psm + OFF_XLO(s) + so) = lv;
        }

        // ---- cp.async W hi/lo tiles (pre-converted fp16) ----
#pragma unroll
        for (int i = 0; i < 4; i++) {
            uint32_t so = sw_off(sr[i], sc);
            CP_ASYNC16(sbase + OFF_WHI(s) + so,
                       Whi + (size_t)(k0 + sr[i]) * DK + sc * 8);
            CP_ASYNC16(sbase + OFF_WLO(s) + so,
                       Wlo + (size_t)(k0 + sr[i]) * DK + sc * 8);
        }
        CP_COMMIT();

        // ---- prefetch next chunk's X into registers (hidden under MMAs) ----
        if (kc + 1 < DMODEL / 64) {
#pragma unroll
            for (int i = 0; i < 4; i++) {
                const float* src = X + (size_t)(row0 + sr[i]) * DMODEL
                                     + (k0 + 64) + sc * 8;
                xa[i] = *reinterpret_cast<const float4*>(src);
                xb[i] = *reinterpret_cast<const float4*>(src + 4);
            }
        }

        CP_WAIT0();
        __syncthreads();

        // ---- A fragments (this warp's 16 rows), hi and lo ----
        uint32_t aHi[4][4], aLo[4][4];
        {
            int arow = w * 16 + (qq & 1) * 8 + rr;
#pragma unroll
            for (int ss = 0; ss < 4; ss++) {
                uint32_t off = sw_off(arow, 2 * ss + (qq >> 1));
                LDSM_X4(aHi[ss][0], aHi[ss][1], aHi[ss][2], aHi[ss][3],
                        sbase + OFF_XHI(s) + off);
                LDSM_X4(aLo[ss][0], aLo[ss][1], aLo[ss][2], aLo[ss][3],
                        sbase + OFF_XLO(s) + off);
            }
        }
        // ---- B fragments + MMAs: hi*hi + lo*hi + hi*lo ----
        int brow_base = qq * 8 + rr;
#pragma unroll
        for (int j = 0; j < 8; j++) {
#pragma unroll
            for (int sp = 0; sp < 2; sp++) {
                int brow = 32 * sp + brow_base;
                uint32_t v0, v1, v2, v3, u0, u1, u2, u3;
                LDSM_X4_T(v0, v1, v2, v3, sbase + OFF_WHI(s) + sw_off(brow, j));
                MMA16816(O[j], aHi[2 * sp],     v0, v1);
                MMA16816(O[j], aHi[2 * sp + 1], v2, v3);
                MMA16816(O[j], aLo[2 * sp],     v0, v1);
                MMA16816(O[j], aLo[2 * sp + 1], v2, v3);
                LDSM_X4_T(u0, u1, u2, u3, sbase + OFF_WLO(s) + sw_off(brow, j));
                MMA16816(O[j], aHi[2 * sp],     u0, u1);
                MMA16816(O[j], aHi[2 * sp + 1], u2, u3);
            }
        }
        // no trailing sync: double-buffered; top-of-loop sync orders reuse
    }

    // ---- epilogue: +bias, (mask*0.125 for q), emit fp16 (v: hi/lo split) ----
    const int row_a = row0 + w * 16 + g;
    const int row_b = row_a + 8;
    const float sca = (which == 0) ? (mask[row_a] * 0.125f) : 1.0f;
    const float scb = (which == 0) ? (mask[row_b] * 0.125f) : 1.0f;
#pragma unroll
    for (int j = 0; j < 8; j++) {
        int col = 8 * j + 2 * t;
        float b0 = bias[col], b1 = bias[col + 1];
        float va0 = (O[j][0] + b0) * sca, va1 = (O[j][1] + b1) * sca;
        float vb0 = (O[j][2] + b0) * scb, vb1 = (O[j][3] + b1) * scb;
        size_t oa = (size_t)row_a * DK + col;
        size_t ob = (size_t)row_b * DK + col;
        if (which == 0) {
            *reinterpret_cast<uint32_t*>(&g_qh[oa]) = pack_h2(va0, va1);
            *reinterpret_cast<uint32_t*>(&g_qh[ob]) = pack_h2(vb0, vb1);
        } else if (which == 1) {
            *reinterpret_cast<uint32_t*>(&g_kh[oa]) = pack_h2(va0, va1);
            *reinterpret_cast<uint32_t*>(&g_kh[ob]) = pack_h2(vb0, vb1);
        } else {
            __half ha0 = __float2half_rn(va0), ha1 = __float2half_rn(va1);
            __half hb0 = __float2half_rn(vb0), hb1 = __float2half_rn(vb1);
            *reinterpret_cast<uint32_t*>(&g_vhi[oa]) =
                pack_h2(__half2float(ha0), __half2float(ha1));
            *reinterpret_cast<uint32_t*>(&g_vhi[ob]) =
                pack_h2(__half2float(hb0), __half2float(hb1));
            *reinterpret_cast<uint32_t*>(&g_vlo[oa]) =
                pack_h2(va0 - __half2float(ha0), va1 - __half2float(ha1));
            *reinterpret_cast<uint32_t*>(&g_vlo[ob]) =
                pack_h2(vb0 - __half2float(hb0), vb1 - __half2float(hb1));
        }
    }
}

// ============================================================================
// FlashAttention (fp16 mma.sync), split-K over gridDim.z=4.
//   No-max softmax is linear in exp() so quarters sum exactly.
// ============================================================================
#define BR   64
#define BC   64
#define NKT_Z (SEQ / BC / ZSPLIT)      // 16 tiles per quarter

#define Q_BYTES     (BR * 128)
#define TILE_BYTES  (BC * 128)
#define STAGE_BYTES (3 * TILE_BYTES)
#define ATTN_SMEM   (Q_BYTES + 2 * STAGE_BYTES)   // 57344

__device__ __forceinline__ void prefetch_tile(char* stage, int b, int key0, int tid)
{
    const __half* srcs[3] = {g_kh, g_vhi, g_vlo};
#pragma unroll
    for (int i = 0; i < 12; i++) {
        int idx = tid + i * 128;
        int arr = idx >> 9;
        int rem = idx & 511;
        int row = rem >> 3, c = rem & 7;
        const __half* g = srcs[arr] + ((size_t)b * SEQ + key0 + row) * DK + c * 8;
        uint32_t d = cvta_smem(stage + arr * TILE_BYTES) + sw_off(row, c);
        CP_ASYNC16(d, g);
    }
}

__global__ __launch_bounds__(128) void attn_kernel()
{
    extern __shared__ char smem[];
    char* Qs = smem;
    char* St = smem + Q_BYTES;

    const int tid  = threadIdx.x;
    const int lane = tid & 31;
    const int w    = tid >> 5;
    const int b    = blockIdx.y;
    const int q0   = blockIdx.x * BR;
    const int z    = blockIdx.z;
    const int key_base = z * (SEQ / ZSPLIT);
    const int g    = lane >> 2;
    const int t    = lane & 3;
    const int qq   = lane >> 3;
    const int rr   = lane & 7;

    prefetch_tile(St, b, key_base, tid);
    CP_COMMIT();

    {
        const __half* qb = g_qh + ((size_t)b * SEQ + q0) * DK;
#pragma unroll
        for (int i = 0; i < 4; i++) {
            int idx = tid + i * 128;
            int row = idx >> 3, c = idx & 7;
            uint4 v = *reinterpret_cast<const uint4*>(qb + (size_t)row * DK + c * 8);
            *reinterpret_cast<uint4*>(Qs + sw_off(row, c)) = v;
        }
    }
    __syncthreads();

    uint32_t qA[4][4];
    {
        uint32_t qbase = cvta_smem(Qs);
        int row = w * 16 + (qq & 1) * 8 + rr;
#pragma unroll
        for (int s = 0; s < 4; s++) {
            uint32_t addr = qbase + sw_off(row, 2 * s + (qq >> 1));
            LDSM_X4(qA[s][0], qA[s][1], qA[s][2], qA[s][3], addr);
        }
    }

    float O[8][4];
#pragma unroll
    for (int j = 0; j < 8; j++)
#pragma unroll
        for (int i = 0; i < 4; i++) O[j][i] = 0.f;
    float L0 = 0.f, L1 = 0.f;

    for (int kt = 0; kt < NKT_Z; kt++) {
        const int s = kt & 1;
        char* stage = St + s * STAGE_BYTES;

        if (kt + 1 < NKT_Z) {
            prefetch_tile(St + (s ^ 1) * STAGE_BYTES, b,
                          key_base + (kt + 1) * BC, tid);
            CP_COMMIT();
            CP_WAIT1();
        } else {
            CP_WAIT0();
        }
        __syncthreads();

        const uint32_t kb  = cvta_smem(stage);
        const uint32_t vhb = kb + TILE_BYTES;
        const uint32_t vlb = kb + 2 * TILE_BYTES;

        uint32_t aPhi[4][4], aPlo[4][4];
#pragma unroll
        for (int j = 0; j < 8; j++) {
            float d[4] = {0.f, 0.f, 0.f, 0.f};
#pragma unroll
            for (int sp = 0; sp < 2; sp++) {
                int row = j * 8 + rr;
                uint32_t addr = kb + sw_off(row, 4 * sp + qq);
                uint32_t k0, k1, k2, k3;
                LDSM_X4(k0, k1, k2, k3, addr);
                MMA16816(d, qA[2 * sp],     k0, k1);
                MMA16816(d, qA[2 * sp + 1], k2, k3);
            }
            float p0 = __expf(d[0]), p1 = __expf(d[1]);
            float p2 = __expf(d[2]), p3 = __expf(d[3]);
            L0 += p0 + p1;
            L1 += p2 + p3;
            __half h0 = __float2half_rn(p0), h1 = __float2half_rn(p1);
            __half h2 = __float2half_rn(p2), h3 = __float2half_rn(p3);
            __half2 hA = __halves2half2(h0, h1);
            __half2 hB = __halves2half2(h2, h3);
            int sp2 = j >> 1, o = (j & 1) * 2;
            aPhi[sp2][o]     = *reinterpret_cast<uint32_t*>(&hA);
            aPhi[sp2][o + 1] = *reinterpret_cast<uint32_t*>(&hB);
            aPlo[sp2][o]     = pack_h2(p0 - __half2float(h0), p1 - __half2float(h1));
            aPlo[sp2][o + 1] = pack_h2(p2 - __half2float(h2), p3 - __half2float(h3));
        }

#pragma unroll
        for (int j = 0; j < 8; j++) {
#pragma unroll
            for (int sp = 0; sp < 2; sp++) {
                int row = 32 * sp + qq * 8 + rr;
                uint32_t v0, v1, v2, v3, u0, u1, u2, u3;
                LDSM_X4_T(v0, v1, v2, v3, vhb + sw_off(row, j));
                MMA16816(O[j], aPhi[2 * sp],     v0, v1);
                MMA16816(O[j], aPhi[2 * sp + 1], v2, v3);
                MMA16816(O[j], aPlo[2 * sp],     v0, v1);
                MMA16816(O[j], aPlo[2 * sp + 1], v2, v3);
                LDSM_X4_T(u0, u1, u2, u3, vlb + sw_off(row, j));
                MMA16816(O[j], aPhi[2 * sp],     u0, u1);
                MMA16816(O[j], aPhi[2 * sp + 1], u2, u3);
            }
        }
        __syncthreads();
    }

    // ---- epilogue: partial (O, L) to this quarter's scratch ----
    L0 += __shfl_xor_sync(0xffffffffu, L0, 1);
    L0 += __shfl_xor_sync(0xffffffffu, L0, 2);
    L1 += __shfl_xor_sync(0xffffffffu, L1, 1);
    L1 += __shfl_xor_sync(0xffffffffu, L1, 2);

    const size_t row_a = (size_t)b * SEQ + q0 + w * 16 + g;
    const size_t row_b = row_a + 8;
    float* Oz = g_Oacc[z];
    if (t == 0) {
        g_Lacc[z][row_a] = L0;
        g_Lacc[z][row_b] = L1;
    }
#pragma unroll
    for (int j = 0; j < 8; j++) {
        int col = 8 * j + 2 * t;
        *reinterpret_cast<float2*>(Oz + row_a * DK + col) =
            make_float2(O[j][0], O[j][1]);
        *reinterpret_cast<float2*>(Oz + row_b * DK + col) =
            make_float2(O[j][2], O[j][3]);
    }
}

// ============================================================================
// Normalize: out = sum_z O_z / sum_z L_z
// ============================================================================
__global__ __launch_bounds__(256) void normalize_kernel(float* __restrict__ out)
{
    int i = blockIdx.x * 256 + threadIdx.x;      // float4 index
    int row = i >> 4;
    float Lsum = 0.f;
#pragma unroll
    for (int z = 0; z < ZSPLIT; z++) Lsum += g_Lacc[z][row];
    float inv = 1.0f / Lsum;
    float4 r = make_float4(0.f, 0.f, 0.f, 0.f);
#pragma unroll
    for (int z = 0; z < ZSPLIT; z++) {
        float4 a = *reinterpret_cast<const float4*>(&g_Oacc[z][(size_t)i * 4]);
        r.x += a.x; r.y += a.y; r.z += a.z; r.w += a.w;
    }
    r.x *= inv; r.y *= inv; r.z *= inv; r.w *= inv;
    *reinterpret_cast<float4*>(out + (size_t)i * 4) = r;
}

// ============================================================================
extern "C" void kernel_launch(void* const* d_in, const int* in_sizes, int n_in,
                              void* d_out, int out_size)
{
    const float* q  = (const float*)d_in[0];
    const float* k  = (const float*)d_in[1];
    const float* v  = (const float*)d_in[2];
    const float* m  = (const float*)d_in[3];
    const float* Wq = (const float*)d_in[4];
    const float* bq = (const float*)d_in[5];
    const float* Wk = (const float*)d_in[6];
    const float* bk = (const float*)d_in[7];
    const float* Wv = (const float*)d_in[8];
    const float* bv = (const float*)d_in[9];
    float* out = (float*)d_out;

    dim3 wgrid(DMODEL * DK / 256, 3);
    wconv_kernel<<<wgrid, 256>>>(Wq, Wk, Wv);

    cudaFuncSetAttribute(proj_mma_kernel,
                         cudaFuncAttributeMaxDynamicSharedMemorySize, PJ_SMEM);
    dim3 pgrid(ROWS / 64, 3);
    proj_mma_kernel<<<pgrid, 128, PJ_SMEM>>>(q, k, v, bq, bk, bv, m);

    cudaFuncSetAttribute(attn_kernel,
                         cudaFuncAttributeMaxDynamicSharedMemorySize, ATTN_SMEM);
    dim3 grid(SEQ / BR, BATCH, ZSPLIT);
    attn_kernel<<<grid, 128, ATTN_SMEM>>>();

    normalize_kernel<<<ROWS * DK / 4 / 256, 256>>>(out);
}

// round 6
// speedup vs baseline: 6.4994x; 1.2173x over previous
#include <cuda_runtime.h>
#include <cuda_fp16.h>
#include <cstdint>

// ============================================================================
// Problem constants
// ============================================================================
#define BATCH   4
#define SEQ     4096
#define DMODEL  1024
#define DK      64
#define ROWS    (BATCH * SEQ)        // 16384

// Projected tensors. q folded with mask*0.125. v plain fp16 (error budgeted).
__device__ __align__(16) __half g_qh [ROWS * DK];
__device__ __align__(16) __half g_kh [ROWS * DK];
__device__ __align__(16) __half g_vh [ROWS * DK];

// Pre-converted weights (hi/lo fp16), 3 projections flat
__device__ __align__(16) __half g_Whi[3 * DMODEL * DK];
__device__ __align__(16) __half g_Wlo[3 * DMODEL * DK];

// split-K attention scratch: 4 quarters write disjoint buffers (deterministic)
#define ZSPLIT 4
__device__ float g_Oacc[ZSPLIT][ROWS * DK];
__device__ float g_Lacc[ZSPLIT][ROWS];

// ============================================================================
// small helpers
// ============================================================================
__device__ __forceinline__ uint32_t cvta_smem(const void* p) {
    return (uint32_t)__cvta_generic_to_shared(p);
}

#define LDSM_X4(r0, r1, r2, r3, addr) \
    asm volatile("ldmatrix.sync.aligned.m8n8.x4.shared.b16 {%0,%1,%2,%3}, [%4];" \
        : "=r"(r0), "=r"(r1), "=r"(r2), "=r"(r3) : "r"(addr))

#define LDSM_X4_T(r0, r1, r2, r3, addr) \
    asm volatile("ldmatrix.sync.aligned.m8n8.x4.trans.shared.b16 {%0,%1,%2,%3}, [%4];" \
        : "=r"(r0), "=r"(r1), "=r"(r2), "=r"(r3) : "r"(addr))

#define MMA16816(d, a, b0, b1) \
    asm volatile("mma.sync.aligned.m16n8k16.row.col.f32.f16.f16.f32 " \
        "{%0,%1,%2,%3}, {%4,%5,%6,%7}, {%8,%9}, {%0,%1,%2,%3};" \
        : "+f"((d)[0]), "+f"((d)[1]), "+f"((d)[2]), "+f"((d)[3]) \
        : "r"((a)[0]), "r"((a)[1]), "r"((a)[2]), "r"((a)[3]), "r"(b0), "r"(b1))

#define CP_ASYNC16(dst, src) \
    asm volatile("cp.async.cg.shared.global [%0], [%1], 16;" \
        :: "r"(dst), "l"(src) : "memory")
#define CP_COMMIT()  asm volatile("cp.async.commit_group;" ::: "memory")
#define CP_WAIT0()   asm volatile("cp.async.wait_group 0;" ::: "memory")
#define CP_WAIT1()   asm volatile("cp.async.wait_group 1;" ::: "memory")

__device__ __forceinline__ uint32_t pack_h2(float a, float b) {
    __half2 h = __floats2half2_rn(a, b);
    return *reinterpret_cast<uint32_t*>(&h);
}

// smem swizzle: row-major fp16 tiles, row = 128B = 8 chunks of 16B.
__device__ __forceinline__ uint32_t sw_off(int row, int chunk) {
    return (uint32_t)(row * 128 + ((chunk ^ (row & 7)) << 4));
}

// ============================================================================
// Weight pre-conversion: fp32 -> fp16 hi + lo residual, once.
// ============================================================================
__global__ __launch_bounds__(256) void wconv_kernel(
    const float* __restrict__ Wq, const float* __restrict__ Wk,
    const float* __restrict__ Wv)
{
    int i = blockIdx.x * 256 + threadIdx.x;
    int which = blockIdx.y;
    const float* W = (which == 0) ? Wq : (which == 1) ? Wk : Wv;
    float v = W[i];
    __half h = __float2half_rn(v);
    g_Whi[which * DMODEL * DK + i] = h;
    g_Wlo[which * DMODEL * DK + i] = __float2half_rn(v - __half2float(h));
}

// ============================================================================
// Tensor-core projection (split-fp16 3-MMA), software-pipelined.
// ============================================================================
#define PJ_TILE 8192
#define PJ_SMEM (8 * PJ_TILE)             // 64KB
#define OFF_XHI(s) ((s) * PJ_TILE)
#define OFF_XLO(s) (16384 + (s) * PJ_TILE)
#define OFF_WHI(s) (32768 + (s) * PJ_TILE)
#define OFF_WLO(s) (49152 + (s) * PJ_TILE)

__global__ __launch_bounds__(128) void proj_mma_kernel(
    const float* __restrict__ Xq, const float* __restrict__ Xk,
    const float* __restrict__ Xv,
    const float* __restrict__ bq, const float* __restrict__ bk,
    const float* __restrict__ bv,
    const float* __restrict__ mask)
{
    extern __shared__ __align__(16) char psm[];
    const uint32_t sbase = cvta_smem(psm);

    const int tid   = threadIdx.x;
    const int lane  = tid & 31;
    const int w     = tid >> 5;
    const int which = blockIdx.y;
    const int row0  = blockIdx.x * 64;
    const int g     = lane >> 2;
    const int t     = lane & 3;
    const int qq    = lane >> 3;
    const int rr    = lane & 7;

    const float* X    = (which == 0) ? Xq : (which == 1) ? Xk : Xv;
    const float* bias = (which == 0) ? bq : (which == 1) ? bk : bv;
    const __half* Whi = g_Whi + which * DMODEL * DK;
    const __half* Wlo = g_Wlo + which * DMODEL * DK;

    const int sr[4] = { (tid) >> 3, (tid + 128) >> 3, (tid + 256) >> 3, (tid + 384) >> 3 };
    const int sc    = tid & 7;

    float O[8][4];
#pragma unroll
    for (int j = 0; j < 8; j++)
#pragma unroll
        for (int i = 0; i < 4; i++) O[j][i] = 0.f;

    float4 xa[4], xb[4];
#pragma unroll
    for (int i = 0; i < 4; i++) {
        const float* src = X + (size_t)(row0 + sr[i]) * DMODEL + sc * 8;
        xa[i] = *reinterpret_cast<const float4*>(src);
        xb[i] = *reinterpret_cast<const float4*>(src + 4);
    }

    for (int kc = 0; kc < DMODEL / 64; kc++) {
        const int s = kc & 1;
        const int k0 = kc * 64;

#pragma unroll
        for (int i = 0; i < 4; i++) {
            float4 a = xa[i], b = xb[i];
            __half h[8];
            h[0]=__float2half_rn(a.x); h[1]=__float2half_rn(a.y);
            h[2]=__float2half_rn(a.z); h[3]=__float2half_rn(a.w);
            h[4]=__float2half_rn(b.x); h[5]=__float2half_rn(b.y);
            h[6]=__float2half_rn(b.z); h[7]=__float2half_rn(b.w);
            uint4 hv, lv;
            hv.x = pack_h2(__half2float(h[0]), __half2float(h[1]));
            hv.y = pack_h2(__half2float(h[2]), __half2float(h[3]));
            hv.z = pack_h2(__half2float(h[4]), __half2float(h[5]));
            hv.w = pack_h2(__half2float(h[6]), __half2float(h[7]));
            lv.x = pack_h2(a.x - __half2float(h[0]), a.y - __half2float(h[1]));
            lv.y = pack_h2(a.z - __half2float(h[2]), a.w - __half2float(h[3]));
            lv.z = pack_h2(b.x - __half2float(h[4]), b.y - __half2float(h[5]));
            lv.w = pack_h2(b.z - __half2float(h[6]), b.w - __half2float(h[7]));
            uint32_t so = sw_off(sr[i], sc);
            *reinterpret_cast<uint4*>(psm + OFF_XHI(s) + so) = hv;
            *reinterpret_cast<uint4*>(psm + OFF_XLO(s) + so) = lv;
        }

#pragma unroll
        for (int i = 0; i < 4; i++) {
            uint32_t so = sw_off(sr[i], sc);
            CP_ASYNC16(sbase + OFF_WHI(s) + so,
                       Whi + (size_t)(k0 + sr[i]) * DK + sc * 8);
            CP_ASYNC16(sbase + OFF_WLO(s) + so,
                       Wlo + (size_t)(k0 + sr[i]) * DK + sc * 8);
        }
        CP_COMMIT();

        if (kc + 1 < DMODEL / 64) {
#pragma unroll
            for (int i = 0; i < 4; i++) {
                const float* src = X + (size_t)(row0 + sr[i]) * DMODEL
                                     + (k0 + 64) + sc * 8;
                xa[i] = *reinterpret_cast<const float4*>(src);
                xb[i] = *reinterpret_cast<const float4*>(src + 4);
            }
        }

        CP_WAIT0();
        __syncthreads();

        uint32_t aHi[4][4], aLo[4][4];
        {
            int arow = w * 16 + (qq & 1) * 8 + rr;
#pragma unroll
            for (int ss = 0; ss < 4; ss++) {
                uint32_t off = sw_off(arow, 2 * ss + (qq >> 1));
                LDSM_X4(aHi[ss][0], aHi[ss][1], aHi[ss][2], aHi[ss][3],
                        sbase + OFF_XHI(s) + off);
                LDSM_X4(aLo[ss][0], aLo[ss][1], aLo[ss][2], aLo[ss][3],
                        sbase + OFF_XLO(s) + off);
            }
        }
        int brow_base = qq * 8 + rr;
#pragma unroll
        for (int j = 0; j < 8; j++) {
#pragma unroll
            for (int sp = 0; sp < 2; sp++) {
                int brow = 32 * sp + brow_base;
                uint32_t v0, v1, v2, v3, u0, u1, u2, u3;
                LDSM_X4_T(v0, v1, v2, v3, sbase + OFF_WHI(s) + sw_off(brow, j));
                MMA16816(O[j], aHi[2 * sp],     v0, v1);
                MMA16816(O[j], aHi[2 * sp + 1], v2, v3);
                MMA16816(O[j], aLo[2 * sp],     v0, v1);
                MMA16816(O[j], aLo[2 * sp + 1], v2, v3);
                LDSM_X4_T(u0, u1, u2, u3, sbase + OFF_WLO(s) + sw_off(brow, j));
                MMA16816(O[j], aHi[2 * sp],     u0, u1);
                MMA16816(O[j], aHi[2 * sp + 1], u2, u3);
            }
        }
    }

    // ---- epilogue: +bias, (mask*0.125 for q), emit fp16 ----
    const int row_a = row0 + w * 16 + g;
    const int row_b = row_a + 8;
    const float sca = (which == 0) ? (mask[row_a] * 0.125f) : 1.0f;
    const float scb = (which == 0) ? (mask[row_b] * 0.125f) : 1.0f;
    __half* Y = (which == 0) ? g_qh : (which == 1) ? g_kh : g_vh;
#pragma unroll
    for (int j = 0; j < 8; j++) {
        int col = 8 * j + 2 * t;
        float b0 = bias[col], b1 = bias[col + 1];
        float va0 = (O[j][0] + b0) * sca, va1 = (O[j][1] + b1) * sca;
        float vb0 = (O[j][2] + b0) * scb, vb1 = (O[j][3] + b1) * scb;
        *reinterpret_cast<uint32_t*>(&Y[(size_t)row_a * DK + col]) = pack_h2(va0, va1);
        *reinterpret_cast<uint32_t*>(&Y[(size_t)row_b * DK + col]) = pack_h2(vb0, vb1);
    }
}

// ============================================================================
// FlashAttention (fp16 mma.sync), split-K over gridDim.z=4.
//   V plain fp16 (error budgeted); P split hi/lo kept (2 PV MMAs + 1 S MMA).
//   40KB smem + <=128 regs -> 4 CTAs/SM.
// ============================================================================
#define BR   64
#define BC   64
#define NKT_Z (SEQ / BC / ZSPLIT)      // 16 tiles per quarter

#define Q_BYTES     (BR * 128)
#define TILE_BYTES  (BC * 128)
#define STAGE_BYTES (2 * TILE_BYTES)               // K + V = 16KB
#define ATTN_SMEM   (Q_BYTES + 2 * STAGE_BYTES)    // 40960

__device__ __forceinline__ void prefetch_tile(char* stage, int b, int key0, int tid)
{
    const __half* srcs[2] = {g_kh, g_vh};
#pragma unroll
    for (int i = 0; i < 8; i++) {
        int idx = tid + i * 128;          // 0..1023
        int arr = idx >> 9;               // 0..1
        int rem = idx & 511;
        int row = rem >> 3, c = rem & 7;
        const __half* g = srcs[arr] + ((size_t)b * SEQ + key0 + row) * DK + c * 8;
        uint32_t d = cvta_smem(stage + arr * TILE_BYTES) + sw_off(row, c);
        CP_ASYNC16(d, g);
    }
}

__global__ __launch_bounds__(128, 4) void attn_kernel()
{
    extern __shared__ char smem[];
    char* Qs = smem;
    char* St = smem + Q_BYTES;

    const int tid  = threadIdx.x;
    const int lane = tid & 31;
    const int w    = tid >> 5;
    const int b    = blockIdx.y;
    const int q0   = blockIdx.x * BR;
    const int z    = blockIdx.z;
    const int key_base = z * (SEQ / ZSPLIT);
    const int g    = lane >> 2;
    const int t    = lane & 3;
    const int qq   = lane >> 3;
    const int rr   = lane & 7;

    prefetch_tile(St, b, key_base, tid);
    CP_COMMIT();

    {
        const __half* qb = g_qh + ((size_t)b * SEQ + q0) * DK;
#pragma unroll
        for (int i = 0; i < 4; i++) {
            int idx = tid + i * 128;
            int row = idx >> 3, c = idx & 7;
            uint4 v = *reinterpret_cast<const uint4*>(qb + (size_t)row * DK + c * 8);
            *reinterpret_cast<uint4*>(Qs + sw_off(row, c)) = v;
        }
    }
    __syncthreads();

    uint32_t qA[4][4];
    {
        uint32_t qbase = cvta_smem(Qs);
        int row = w * 16 + (qq & 1) * 8 + rr;
#pragma unroll
        for (int s = 0; s < 4; s++) {
            uint32_t addr = qbase + sw_off(row, 2 * s + (qq >> 1));
            LDSM_X4(qA[s][0], qA[s][1], qA[s][2], qA[s][3], addr);
        }
    }

    float O[8][4];
#pragma unroll
    for (int j = 0; j < 8; j++)
#pragma unroll
        for (int i = 0; i < 4; i++) O[j][i] = 0.f;
    float L0 = 0.f, L1 = 0.f;

    for (int kt = 0; kt < NKT_Z; kt++) {
        const int s = kt & 1;
        char* stage = St + s * STAGE_BYTES;

        if (kt + 1 < NKT_Z) {
            prefetch_tile(St + (s ^ 1) * STAGE_BYTES, b,
                          key_base + (kt + 1) * BC, tid);
            CP_COMMIT();
            CP_WAIT1();
        } else {
            CP_WAIT0();
        }
        __syncthreads();

        const uint32_t kb  = cvta_smem(stage);
        const uint32_t vhb = kb + TILE_BYTES;

        uint32_t aPhi[4][4], aPlo[4][4];
#pragma unroll
        for (int j = 0; j < 8; j++) {
            float d[4] = {0.f, 0.f, 0.f, 0.f};
#pragma unroll
            for (int sp = 0; sp < 2; sp++) {
                int row = j * 8 + rr;
                uint32_t addr = kb + sw_off(row, 4 * sp + qq);
                uint32_t k0, k1, k2, k3;
                LDSM_X4(k0, k1, k2, k3, addr);
                MMA16816(d, qA[2 * sp],     k0, k1);
                MMA16816(d, qA[2 * sp + 1], k2, k3);
            }
            float p0 = __expf(d[0]), p1 = __expf(d[1]);
            float p2 = __expf(d[2]), p3 = __expf(d[3]);
            L0 += p0 + p1;
            L1 += p2 + p3;
            __half h0 = __float2half_rn(p0), h1 = __float2half_rn(p1);
            __half h2 = __float2half_rn(p2), h3 = __float2half_rn(p3);
            __half2 hA = __halves2half2(h0, h1);
            __half2 hB = __halves2half2(h2, h3);
            int sp2 = j >> 1, o = (j & 1) * 2;
            aPhi[sp2][o]     = *reinterpret_cast<uint32_t*>(&hA);
            aPhi[sp2][o + 1] = *reinterpret_cast<uint32_t*>(&hB);
            aPlo[sp2][o]     = pack_h2(p0 - __half2float(h0), p1 - __half2float(h1));
            aPlo[sp2][o + 1] = pack_h2(p2 - __half2float(h2), p3 - __half2float(h3));
        }

#pragma unroll
        for (int j = 0; j < 8; j++) {
#pragma unroll
            for (int sp = 0; sp < 2; sp++) {
                int row = 32 * sp + qq * 8 + rr;
                uint32_t v0, v1, v2, v3;
                LDSM_X4_T(v0, v1, v2, v3, vhb + sw_off(row, j));
                MMA16816(O[j], aPhi[2 * sp],     v0, v1);
                MMA16816(O[j], aPhi[2 * sp + 1], v2, v3);
                MMA16816(O[j], aPlo[2 * sp],     v0, v1);
                MMA16816(O[j], aPlo[2 * sp + 1], v2, v3);
            }
        }
        __syncthreads();
    }

    // ---- epilogue: partial (O, L) to this quarter's scratch ----
    L0 += __shfl_xor_sync(0xffffffffu, L0, 1);
    L0 += __shfl_xor_sync(0xffffffffu, L0, 2);
    L1 += __shfl_xor_sync(0xffffffffu, L1, 1);
    L1 += __shfl_xor_sync(0xffffffffu, L1, 2);

    const size_t row_a = (size_t)b * SEQ + q0 + w * 16 + g;
    const size_t row_b = row_a + 8;
    float* Oz = g_Oacc[z];
    if (t == 0) {
        g_Lacc[z][row_a] = L0;
        g_Lacc[z][row_b] = L1;
    }
#pragma unroll
    for (int j = 0; j < 8; j++) {
        int col = 8 * j + 2 * t;
        *reinterpret_cast<float2*>(Oz + row_a * DK + col) =
            make_float2(O[j][0], O[j][1]);
        *reinterpret_cast<float2*>(Oz + row_b * DK + col) =
            make_float2(O[j][2], O[j][3]);
    }
}

// ============================================================================
// Normalize: out = sum_z O_z / sum_z L_z
// ============================================================================
__global__ __launch_bounds__(256) void normalize_kernel(float* __restrict__ out)
{
    int i = blockIdx.x * 256 + threadIdx.x;
    int row = i >> 4;
    float Lsum = 0.f;
#pragma unroll
    for (int z = 0; z < ZSPLIT; z++) Lsum += g_Lacc[z][row];
    float inv = 1.0f / Lsum;
    float4 r = make_float4(0.f, 0.f, 0.f, 0.f);
#pragma unroll
    for (int z = 0; z < ZSPLIT; z++) {
        float4 a = *reinterpret_cast<const float4*>(&g_Oacc[z][(size_t)i * 4]);
        r.x += a.x; r.y += a.y; r.z += a.z; r.w += a.w;
    }
    r.x *= inv; r.y *= inv; r.z *= inv; r.w *= inv;
    *reinterpret_cast<float4*>(out + (size_t)i * 4) = r;
}

// ============================================================================
extern "C" void kernel_launch(void* const* d_in, const int* in_sizes, int n_in,
                              void* d_out, int out_size)
{
    const float* q  = (const float*)d_in[0];
    const float* k  = (const float*)d_in[1];
    const float* v  = (const float*)d_in[2];
    const float* m  = (const float*)d_in[3];
    const float* Wq = (const float*)d_in[4];
    const float* bq = (const float*)d_in[5];
    const float* Wk = (const float*)d_in[6];
    const float* bk = (const float*)d_in[7];
    const float* Wv = (const float*)d_in[8];
    const float* bv = (const float*)d_in[9];
    float* out = (float*)d_out;

    dim3 wgrid(DMODEL * DK / 256, 3);
    wconv_kernel<<<wgrid, 256>>>(Wq, Wk, Wv);

    cudaFuncSetAttribute(proj_mma_kernel,
                         cudaFuncAttributeMaxDynamicSharedMemorySize, PJ_SMEM);
    dim3 pgrid(ROWS / 64, 3);
    proj_mma_kernel<<<pgrid, 128, PJ_SMEM>>>(q, k, v, bq, bk, bv, m);

    cudaFuncSetAttribute(attn_kernel,
                         cudaFuncAttributeMaxDynamicSharedMemorySize, ATTN_SMEM);
    dim3 grid(SEQ / BR, BATCH, ZSPLIT);
    attn_kernel<<<grid, 128, ATTN_SMEM>>>();

    normalize_kernel<<<ROWS * DK / 4 / 256, 256>>>(out);
}

// round 7
// speedup vs baseline: 7.5001x; 1.1540x over previous
#include <cuda_runtime.h>
#include <cuda_fp16.h>
#include <cstdint>

// ============================================================================
// Problem constants
// ============================================================================
#define BATCH   4
#define SEQ     4096
#define DMODEL  1024
#define DK      64
#define ROWS    (BATCH * SEQ)        // 16384

// Projected tensors. q folded with mask*0.125. v plain fp16 (error budgeted).
__device__ __align__(16) __half g_qh [ROWS * DK];
__device__ __align__(16) __half g_kh [ROWS * DK];
__device__ __align__(16) __half g_vh [ROWS * DK];

// Pre-converted weights (hi/lo fp16), 3 projections flat
__device__ __align__(16) __half g_Whi[3 * DMODEL * DK];
__device__ __align__(16) __half g_Wlo[3 * DMODEL * DK];

// split-K attention scratch: 4 quarters write disjoint buffers (deterministic)
#define ZSPLIT 4
__device__ float g_Oacc[ZSPLIT][ROWS * DK];
__device__ float g_Lacc[ZSPLIT][ROWS];

// ============================================================================
// small helpers
// ============================================================================
__device__ __forceinline__ uint32_t cvta_smem(const void* p) {
    return (uint32_t)__cvta_generic_to_shared(p);
}

#define LDSM_X4(r0, r1, r2, r3, addr) \
    asm volatile("ldmatrix.sync.aligned.m8n8.x4.shared.b16 {%0,%1,%2,%3}, [%4];" \
        : "=r"(r0), "=r"(r1), "=r"(r2), "=r"(r3) : "r"(addr))

#define LDSM_X4_T(r0, r1, r2, r3, addr) \
    asm volatile("ldmatrix.sync.aligned.m8n8.x4.trans.shared.b16 {%0,%1,%2,%3}, [%4];" \
        : "=r"(r0), "=r"(r1), "=r"(r2), "=r"(r3) : "r"(addr))

#define MMA16816(d, a, b0, b1) \
    asm volatile("mma.sync.aligned.m16n8k16.row.col.f32.f16.f16.f32 " \
        "{%0,%1,%2,%3}, {%4,%5,%6,%7}, {%8,%9}, {%0,%1,%2,%3};" \
        : "+f"((d)[0]), "+f"((d)[1]), "+f"((d)[2]), "+f"((d)[3]) \
        : "r"((a)[0]), "r"((a)[1]), "r"((a)[2]), "r"((a)[3]), "r"(b0), "r"(b1))

#define CP_ASYNC16(dst, src) \
    asm volatile("cp.async.cg.shared.global [%0], [%1], 16;" \
        :: "r"(dst), "l"(src) : "memory")
#define CP_COMMIT()  asm volatile("cp.async.commit_group;" ::: "memory")
#define CP_WAIT0()   asm volatile("cp.async.wait_group 0;" ::: "memory")
#define CP_WAIT1()   asm volatile("cp.async.wait_group 1;" ::: "memory")

__device__ __forceinline__ uint32_t pack_h2(float a, float b) {
    __half2 h = __floats2half2_rn(a, b);
    return *reinterpret_cast<uint32_t*>(&h);
}

// smem swizzle: row-major fp16 tiles, row = 128B = 8 chunks of 16B.
__device__ __forceinline__ uint32_t sw_off(int row, int chunk) {
    return (uint32_t)(row * 128 + ((chunk ^ (row & 7)) << 4));
}

// ============================================================================
// Weight pre-conversion: fp32 -> fp16 hi + lo residual, once.
// ============================================================================
__global__ __launch_bounds__(256) void wconv_kernel(
    const float* __restrict__ Wq, const float* __restrict__ Wk,
    const float* __restrict__ Wv)
{
    int i = blockIdx.x * 256 + threadIdx.x;
    int which = blockIdx.y;
    const float* W = (which == 0) ? Wq : (which == 1) ? Wk : Wv;
    float v = W[i];
    __half h = __float2half_rn(v);
    g_Whi[which * DMODEL * DK + i] = h;
    g_Wlo[which * DMODEL * DK + i] = __float2half_rn(v - __half2float(h));
}

// ============================================================================
// Tensor-core projection (split-fp16 3-MMA), software-pipelined.
// ============================================================================
#define PJ_TILE 8192
#define PJ_SMEM (8 * PJ_TILE)             // 64KB
#define OFF_XHI(s) ((s) * PJ_TILE)
#define OFF_XLO(s) (16384 + (s) * PJ_TILE)
#define OFF_WHI(s) (32768 + (s) * PJ_TILE)
#define OFF_WLO(s) (49152 + (s) * PJ_TILE)

__global__ __launch_bounds__(128) void proj_mma_kernel(
    const float* __restrict__ Xq, const float* __restrict__ Xk,
    const float* __restrict__ Xv,
    const float* __restrict__ bq, const float* __restrict__ bk,
    const float* __restrict__ bv,
    const float* __restrict__ mask)
{
    extern __shared__ __align__(16) char psm[];
    const uint32_t sbase = cvta_smem(psm);

    const int tid   = threadIdx.x;
    const int lane  = tid & 31;
    const int w     = tid >> 5;
    const int which = blockIdx.y;
    const int row0  = blockIdx.x * 64;
    const int g     = lane >> 2;
    const int t     = lane & 3;
    const int qq    = lane >> 3;
    const int rr    = lane & 7;

    const float* X    = (which == 0) ? Xq : (which == 1) ? Xk : Xv;
    const float* bias = (which == 0) ? bq : (which == 1) ? bk : bv;
    const __half* Whi = g_Whi + which * DMODEL * DK;
    const __half* Wlo = g_Wlo + which * DMODEL * DK;

    const int sr[4] = { (tid) >> 3, (tid + 128) >> 3, (tid + 256) >> 3, (tid + 384) >> 3 };
    const int sc    = tid & 7;

    float O[8][4];
#pragma unroll
    for (int j = 0; j < 8; j++)
#pragma unroll
        for (int i = 0; i < 4; i++) O[j][i] = 0.f;

    float4 xa[4], xb[4];
#pragma unroll
    for (int i = 0; i < 4; i++) {
        const float* src = X + (size_t)(row0 + sr[i]) * DMODEL + sc * 8;
        xa[i] = *reinterpret_cast<const float4*>(src);
        xb[i] = *reinterpret_cast<const float4*>(src + 4);
    }

    for (int kc = 0; kc < DMODEL / 64; kc++) {
        const int s = kc & 1;
        const int k0 = kc * 64;

#pragma unroll
        for (int i = 0; i < 4; i++) {
            float4 a = xa[i], b = xb[i];
            __half h[8];
            h[0]=__float2half_rn(a.x); h[1]=__float2half_rn(a.y);
            h[2]=__float2half_rn(a.z); h[3]=__float2half_rn(a.w);
            h[4]=__float2half_rn(b.x); h[5]=__float2half_rn(b.y);
            h[6]=__float2half_rn(b.z); h[7]=__float2half_rn(b.w);
            uint4 hv, lv;
            hv.x = pack_h2(__half2float(h[0]), __half2float(h[1]));
            hv.y = pack_h2(__half2float(h[2]), __half2float(h[3]));
            hv.z = pack_h2(__half2float(h[4]), __half2float(h[5]));
            hv.w = pack_h2(__half2float(h[6]), __half2float(h[7]));
            lv.x = pack_h2(a.x - __half2float(h[0]), a.y - __half2float(h[1]));
            lv.y = pack_h2(a.z - __half2float(h[2]), a.w - __half2float(h[3]));
            lv.z = pack_h2(b.x - __half2float(h[4]), b.y - __half2float(h[5]));
            lv.w = pack_h2(b.z - __half2float(h[6]), b.w - __half2float(h[7]));
            uint32_t so = sw_off(sr[i], sc);
            *reinterpret_cast<uint4*>(psm + OFF_XHI(s) + so) = hv;
            *reinterpret_cast<uint4*>(psm + OFF_XLO(s) + so) = lv;
        }

#pragma unroll
        for (int i = 0; i < 4; i++) {
            uint32_t so = sw_off(sr[i], sc);
            CP_ASYNC16(sbase + OFF_WHI(s) + so,
                       Whi + (size_t)(k0 + sr[i]) * DK + sc * 8);
            CP_ASYNC16(sbase + OFF_WLO(s) + so,
                       Wlo + (size_t)(k0 + sr[i]) * DK + sc * 8);
        }
        CP_COMMIT();

        if (kc + 1 < DMODEL / 64) {
#pragma unroll
            for (int i = 0; i < 4; i++) {
                const float* src = X + (size_t)(row0 + sr[i]) * DMODEL
                                     + (k0 + 64) + sc * 8;
                xa[i] = *reinterpret_cast<const float4*>(src);
                xb[i] = *reinterpret_cast<const float4*>(src + 4);
            }
        }

        CP_WAIT0();
        __syncthreads();

        uint32_t aHi[4][4], aLo[4][4];
        {
            int arow = w * 16 + (qq & 1) * 8 + rr;
#pragma unroll
            for (int ss = 0; ss < 4; ss++) {
                uint32_t off = sw_off(arow, 2 * ss + (qq >> 1));
                LDSM_X4(aHi[ss][0], aHi[ss][1], aHi[ss][2], aHi[ss][3],
                        sbase + OFF_XHI(s) + off);
                LDSM_X4(aLo[ss][0], aLo[ss][1], aLo[ss][2], aLo[ss][3],
                        sbase + OFF_XLO(s) + off);
            }
        }
        int brow_base = qq * 8 + rr;
#pragma unroll
        for (int j = 0; j < 8; j++) {
#pragma unroll
            for (int sp = 0; sp < 2; sp++) {
                int brow = 32 * sp + brow_base;
                uint32_t v0, v1, v2, v3, u0, u1, u2, u3;
                LDSM_X4_T(v0, v1, v2, v3, sbase + OFF_WHI(s) + sw_off(brow, j));
                MMA16816(O[j], aHi[2 * sp],     v0, v1);
                MMA16816(O[j], aHi[2 * sp + 1], v2, v3);
                MMA16816(O[j], aLo[2 * sp],     v0, v1);
                MMA16816(O[j], aLo[2 * sp + 1], v2, v3);
                LDSM_X4_T(u0, u1, u2, u3, sbase + OFF_WLO(s) + sw_off(brow, j));
                MMA16816(O[j], aHi[2 * sp],     u0, u1);
                MMA16816(O[j], aHi[2 * sp + 1], u2, u3);
            }
        }
    }

    // ---- epilogue: +bias, (mask*0.125 for q), emit fp16 ----
    const int row_a = row0 + w * 16 + g;
    const int row_b = row_a + 8;
    const float sca = (which == 0) ? (mask[row_a] * 0.125f) : 1.0f;
    const float scb = (which == 0) ? (mask[row_b] * 0.125f) : 1.0f;
    __half* Y = (which == 0) ? g_qh : (which == 1) ? g_kh : g_vh;
#pragma unroll
    for (int j = 0; j < 8; j++) {
        int col = 8 * j + 2 * t;
        float b0 = bias[col], b1 = bias[col + 1];
        float va0 = (O[j][0] + b0) * sca, va1 = (O[j][1] + b1) * sca;
        float vb0 = (O[j][2] + b0) * scb, vb1 = (O[j][3] + b1) * scb;
        *reinterpret_cast<uint32_t*>(&Y[(size_t)row_a * DK + col]) = pack_h2(va0, va1);
        *reinterpret_cast<uint32_t*>(&Y[(size_t)row_b * DK + col]) = pack_h2(vb0, vb1);
    }
}

// ============================================================================
// FlashAttention (fp16 mma.sync), split-K over gridDim.z=4.
//   V and P plain fp16 (error budgeted; measured slack supports it).
//   Per tile per warp: 32 LDSM + 64 MMA -> 32 LDSM + 64->64 total MMAs:
//   S: 32 MMA, PV: 32 MMA.
// ============================================================================
#define BR   64
#define BC   64
#define NKT_Z (SEQ / BC / ZSPLIT)      // 16 tiles per quarter

#define Q_BYTES     (BR * 128)
#define TILE_BYTES  (BC * 128)
#define STAGE_BYTES (2 * TILE_BYTES)               // K + V = 16KB
#define ATTN_SMEM   (Q_BYTES + 2 * STAGE_BYTES)    // 40960

__device__ __forceinline__ void prefetch_tile(char* stage, int b, int key0, int tid)
{
    const __half* srcs[2] = {g_kh, g_vh};
#pragma unroll
    for (int i = 0; i < 8; i++) {
        int idx = tid + i * 128;          // 0..1023
        int arr = idx >> 9;               // 0..1
        int rem = idx & 511;
        int row = rem >> 3, c = rem & 7;
        const __half* g = srcs[arr] + ((size_t)b * SEQ + key0 + row) * DK + c * 8;
        uint32_t d = cvta_smem(stage + arr * TILE_BYTES) + sw_off(row, c);
        CP_ASYNC16(d, g);
    }
}

__global__ __launch_bounds__(128, 4) void attn_kernel()
{
    extern __shared__ char smem[];
    char* Qs = smem;
    char* St = smem + Q_BYTES;

    const int tid  = threadIdx.x;
    const int lane = tid & 31;
    const int w    = tid >> 5;
    const int b    = blockIdx.y;
    const int q0   = blockIdx.x * BR;
    const int z    = blockIdx.z;
    const int key_base = z * (SEQ / ZSPLIT);
    const int g    = lane >> 2;
    const int t    = lane & 3;
    const int qq   = lane >> 3;
    const int rr   = lane & 7;

    prefetch_tile(St, b, key_base, tid);
    CP_COMMIT();

    {
        const __half* qb = g_qh + ((size_t)b * SEQ + q0) * DK;
#pragma unroll
        for (int i = 0; i < 4; i++) {
            int idx = tid + i * 128;
            int row = idx >> 3, c = idx & 7;
            uint4 v = *reinterpret_cast<const uint4*>(qb + (size_t)row * DK + c * 8);
            *reinterpret_cast<uint4*>(Qs + sw_off(row, c)) = v;
        }
    }
    __syncthreads();

    uint32_t qA[4][4];
    {
        uint32_t qbase = cvta_smem(Qs);
        int row = w * 16 + (qq & 1) * 8 + rr;
#pragma unroll
        for (int s = 0; s < 4; s++) {
            uint32_t addr = qbase + sw_off(row, 2 * s + (qq >> 1));
            LDSM_X4(qA[s][0], qA[s][1], qA[s][2], qA[s][3], addr);
        }
    }

    float O[8][4];
#pragma unroll
    for (int j = 0; j < 8; j++)
#pragma unroll
        for (int i = 0; i < 4; i++) O[j][i] = 0.f;
    float L0 = 0.f, L1 = 0.f;

    for (int kt = 0; kt < NKT_Z; kt++) {
        const int s = kt & 1;
        char* stage = St + s * STAGE_BYTES;

        if (kt + 1 < NKT_Z) {
            prefetch_tile(St + (s ^ 1) * STAGE_BYTES, b,
                          key_base + (kt + 1) * BC, tid);
            CP_COMMIT();
            CP_WAIT1();
        } else {
            CP_WAIT0();
        }
        __syncthreads();

        const uint32_t kb  = cvta_smem(stage);
        const uint32_t vhb = kb + TILE_BYTES;

        // ---- S = Q @ K^T, exp -> P fragments (plain fp16) ----
        uint32_t aP[4][4];
#pragma unroll
        for (int j = 0; j < 8; j++) {
            float d[4] = {0.f, 0.f, 0.f, 0.f};
#pragma unroll
            for (int sp = 0; sp < 2; sp++) {
                int row = j * 8 + rr;
                uint32_t addr = kb + sw_off(row, 4 * sp + qq);
                uint32_t k0, k1, k2, k3;
                LDSM_X4(k0, k1, k2, k3, addr);
                MMA16816(d, qA[2 * sp],     k0, k1);
                MMA16816(d, qA[2 * sp + 1], k2, k3);
            }
            float p0 = __expf(d[0]), p1 = __expf(d[1]);
            float p2 = __expf(d[2]), p3 = __expf(d[3]);
            L0 += p0 + p1;
            L1 += p2 + p3;
            int sp2 = j >> 1, o = (j & 1) * 2;
            aP[sp2][o]     = pack_h2(p0, p1);
            aP[sp2][o + 1] = pack_h2(p2, p3);
        }

        // ---- O += P @ V ----
#pragma unroll
        for (int j = 0; j < 8; j++) {
#pragma unroll
            for (int sp = 0; sp < 2; sp++) {
                int row = 32 * sp + qq * 8 + rr;
                uint32_t v0, v1, v2, v3;
                LDSM_X4_T(v0, v1, v2, v3, vhb + sw_off(row, j));
                MMA16816(O[j], aP[2 * sp],     v0, v1);
                MMA16816(O[j], aP[2 * sp + 1], v2, v3);
            }
        }
        __syncthreads();
    }

    // ---- epilogue: partial (O, L) to this quarter's scratch ----
    L0 += __shfl_xor_sync(0xffffffffu, L0, 1);
    L0 += __shfl_xor_sync(0xffffffffu, L0, 2);
    L1 += __shfl_xor_sync(0xffffffffu, L1, 1);
    L1 += __shfl_xor_sync(0xffffffffu, L1, 2);

    const size_t row_a = (size_t)b * SEQ + q0 + w * 16 + g;
    const size_t row_b = row_a + 8;
    float* Oz = g_Oacc[z];
    if (t == 0) {
        g_Lacc[z][row_a] = L0;
        g_Lacc[z][row_b] = L1;
    }
#pragma unroll
    for (int j = 0; j < 8; j++) {
        int col = 8 * j + 2 * t;
        *reinterpret_cast<float2*>(Oz + row_a * DK + col) =
            make_float2(O[j][0], O[j][1]);
        *reinterpret_cast<float2*>(Oz + row_b * DK + col) =
            make_float2(O[j][2], O[j][3]);
    }
}

// ============================================================================
// Normalize: out = sum_z O_z / sum_z L_z
// ============================================================================
__global__ __launch_bounds__(256) void normalize_kernel(float* __restrict__ out)
{
    int i = blockIdx.x * 256 + threadIdx.x;
    int row = i >> 4;
    float Lsum = 0.f;
#pragma unroll
    for (int z = 0; z < ZSPLIT; z++) Lsum += g_Lacc[z][row];
    float inv = 1.0f / Lsum;
    float4 r = make_float4(0.f, 0.f, 0.f, 0.f);
#pragma unroll
    for (int z = 0; z < ZSPLIT; z++) {
        float4 a = *reinterpret_cast<const float4*>(&g_Oacc[z][(size_t)i * 4]);
        r.x += a.x; r.y += a.y; r.z += a.z; r.w += a.w;
    }
    r.x *= inv; r.y *= inv; r.z *= inv; r.w *= inv;
    *reinterpret_cast<float4*>(out + (size_t)i * 4) = r;
}

// ============================================================================
extern "C" void kernel_launch(void* const* d_in, const int* in_sizes, int n_in,
                              void* d_out, int out_size)
{
    const float* q  = (const float*)d_in[0];
    const float* k  = (const float*)d_in[1];
    const float* v  = (const float*)d_in[2];
    const float* m  = (const float*)d_in[3];
    const float* Wq = (const float*)d_in[4];
    const float* bq = (const float*)d_in[5];
    const float* Wk = (const float*)d_in[6];
    const float* bk = (const float*)d_in[7];
    const float* Wv = (const float*)d_in[8];
    const float* bv = (const float*)d_in[9];
    float* out = (float*)d_out;

    dim3 wgrid(DMODEL * DK / 256, 3);
    wconv_kernel<<<wgrid, 256>>>(Wq, Wk, Wv);

    cudaFuncSetAttribute(proj_mma_kernel,
                         cudaFuncAttributeMaxDynamicSharedMemorySize, PJ_SMEM);
    dim3 pgrid(ROWS / 64, 3);
    proj_mma_kernel<<<pgrid, 128, PJ_SMEM>>>(q, k, v, bq, bk, bv, m);

    cudaFuncSetAttribute(attn_kernel,
                         cudaFuncAttributeMaxDynamicSharedMemorySize, ATTN_SMEM);
    dim3 grid(SEQ / BR, BATCH, ZSPLIT);
    attn_kernel<<<grid, 128, ATTN_SMEM>>>();

    normalize_kernel<<<ROWS * DK / 4 / 256, 256>>>(out);
}